// round 13
// baseline (speedup 1.0000x reference)
#include <cuda_runtime.h>
#include <cuda_bf16.h>
#include <math.h>
#include <stdint.h>

// ---------------- problem constants ----------------
#define NN 50000
#define EE 400000
#define HH 8
#define CC 128
#define EMB 256
#define NG 64
#define NOUT 3328
#define NREAL 3200
#define OFF_K 1024
#define OFF_V 2048
#define OFF_S 3072
#define KV_W 2048
#define QB_W 1024

// ---------------- scratch ----------------
__device__ __nv_bfloat16 g_hb[(size_t)NN * EMB];
__device__ __nv_bfloat16 g_qb[(size_t)NN * QB_W];
__device__ __nv_bfloat16 g_kv[(size_t)NN * KV_W];
__device__ float g_skip[(size_t)NN * CC];
__device__ __nv_bfloat16 g_h1[(size_t)NN * CC];
__device__ __nv_bfloat16 g_h2[(size_t)NN * CC];
__device__ __nv_bfloat16 g_Wt[(size_t)NOUT * EMB];
__device__ float g_bcat[NOUT];
__device__ float g_pool[NG * CC];
__device__ float g_cnt[NG];
__device__ int   g_deg[NN];
__device__ int   g_rowptr[NN + 1];
__device__ int   g_wofs[NN + 1];
__device__ int   g_col[EE];
__device__ int   g_bsum[256];
__device__ int   g_bsum2[256];

// ---------------- CSR build ----------------
__global__ void hist_kernel(const int* __restrict__ dst, int* __restrict__ deg, int E) {
    int e = blockIdx.x * blockDim.x + threadIdx.x;
    if (e < E) atomicAdd(&deg[dst[e]], 1);
}

__global__ void scan_block_kernel(const int* __restrict__ deg, int* __restrict__ rowptr,
                                  int* __restrict__ bsum, int n) {
    __shared__ int s[256];
    int i = blockIdx.x * 256 + threadIdx.x;
    int v = (i < n) ? deg[i] : 0;
    s[threadIdx.x] = v;
    __syncthreads();
    #pragma unroll
    for (int off = 1; off < 256; off <<= 1) {
        int t = (threadIdx.x >= off) ? s[threadIdx.x - off] : 0;
        __syncthreads();
        s[threadIdx.x] += t;
        __syncthreads();
    }
    if (i < n) rowptr[i + 1] = s[threadIdx.x];
    if (threadIdx.x == 255) bsum[blockIdx.x] = s[255];
}

__global__ void scan_bsum_kernel(const int* __restrict__ bsum, int* __restrict__ bsum2, int nb) {
    __shared__ int s[256];
    int t = threadIdx.x;
    int v = (t < nb) ? bsum[t] : 0;
    s[t] = v;
    __syncthreads();
    #pragma unroll
    for (int off = 1; off < 256; off <<= 1) {
        int x = (t >= off) ? s[t - off] : 0;
        __syncthreads();
        s[t] += x;
        __syncthreads();
    }
    if (t < nb) bsum2[t] = s[t] - v;   // exclusive
}

__global__ void scan_add_kernel(int* __restrict__ rowptr, const int* __restrict__ bsum2,
                                int* __restrict__ wofs, int n) {
    int i = blockIdx.x * 256 + threadIdx.x;
    if (i < n) {
        int v = rowptr[i + 1] + bsum2[blockIdx.x];
        rowptr[i + 1] = v;
        wofs[i + 1] = v;
    }
    if (i == 0) { rowptr[0] = 0; wofs[0] = 0; }
}

__global__ void scatter_kernel(const int* __restrict__ src, const int* __restrict__ dst,
                               int* __restrict__ wofs, int* __restrict__ col, int E) {
    int e = blockIdx.x * blockDim.x + threadIdx.x;
    if (e < E) {
        int p = atomicAdd(&wofs[dst[e]], 1);
        col[p] = src[e];
    }
}

// ---------------- embedding gather ----------------
__global__ void embed_kernel(const int* __restrict__ x, const float* __restrict__ emb,
                             __nv_bfloat16* __restrict__ hb, int N) {
    int idx = blockIdx.x * blockDim.x + threadIdx.x;
    if (idx >= N * 32) return;
    int n  = idx >> 5;
    int g8 = (idx & 31) << 3;
    const float* p = emb + (size_t)x[n] * EMB + g8;
    float4 a = *(const float4*)p;
    float4 b = *(const float4*)(p + 4);
    __nv_bfloat162 o[4];
    o[0] = __float22bfloat162_rn(make_float2(a.x, a.y));
    o[1] = __float22bfloat162_rn(make_float2(a.z, a.w));
    o[2] = __float22bfloat162_rn(make_float2(b.x, b.y));
    o[3] = __float22bfloat162_rn(make_float2(b.z, b.w));
    *(uint4*)(hb + (size_t)n * EMB + g8) = *(uint4*)o;
}

// ---------------- weight pack: tiled transpose ----------------
__global__ void pack_kernel(const float* __restrict__ Wq, const float* __restrict__ Wk,
                            const float* __restrict__ Wv, const float* __restrict__ Ws,
                            const float* __restrict__ bq, const float* __restrict__ bk,
                            const float* __restrict__ bv, const float* __restrict__ bs,
                            __nv_bfloat16* __restrict__ Wt, float* __restrict__ bcat, int K) {
    __shared__ float t[32][33];
    int n0 = blockIdx.x * 32, k0 = blockIdx.y * 32;
    int tx = threadIdx.x, ty = threadIdx.y;
    #pragma unroll
    for (int i = 0; i < 4; i++) {
        int k = k0 + ty + i * 8;
        int n = n0 + tx;
        float v;
        if (n < 1024)       v = Wq[k * 1024 + n];
        else if (n < 2048)  v = Wk[k * 1024 + (n - 1024)];
        else if (n < 3072)  v = Wv[k * 1024 + (n - 2048)];
        else if (n < NREAL) v = Ws[k * 128  + (n - 3072)];
        else                v = 0.f;
        t[ty + i * 8][tx] = v;
    }
    if (k0 == 0 && ty == 0) {
        int n = n0 + tx;
        float b;
        if (n < 1024)       b = bq[n];
        else if (n < 2048)  b = bk[n - 1024];
        else if (n < 3072)  b = bv[n - 2048];
        else if (n < NREAL) b = bs[n - 3072];
        else                b = 0.f;
        bcat[n] = b;
    }
    __syncthreads();
    #pragma unroll
    for (int i = 0; i < 4; i++) {
        int n = n0 + ty + i * 8;
        int k = k0 + tx;
        Wt[(size_t)n * K + k] = __float2bfloat16(t[tx][ty + i * 8]);
    }
}

// ---------------- bf16 GEMM: 128x128x32, 3-stage cp.async, ldmatrix, 2 CTAs/SM ----------------
__device__ __forceinline__ void mma_bf16(float* c, const uint32_t* a, const uint32_t* b) {
    asm volatile(
        "mma.sync.aligned.m16n8k16.row.col.f32.bf16.bf16.f32 "
        "{%0,%1,%2,%3}, {%4,%5,%6,%7}, {%8,%9}, {%0,%1,%2,%3};"
        : "+f"(c[0]), "+f"(c[1]), "+f"(c[2]), "+f"(c[3])
        : "r"(a[0]), "r"(a[1]), "r"(a[2]), "r"(a[3]), "r"(b[0]), "r"(b[1]));
}

__device__ __forceinline__ void cp16(uint32_t dst, const void* src) {
    asm volatile("cp.async.cg.shared.global [%0], [%1], 16;" :: "r"(dst), "l"(src));
}

__device__ __forceinline__ void ldsm4(uint32_t& r0, uint32_t& r1, uint32_t& r2, uint32_t& r3,
                                      uint32_t addr) {
    asm volatile("ldmatrix.sync.aligned.m8n8.x4.shared.b16 {%0,%1,%2,%3}, [%4];"
        : "=r"(r0), "=r"(r1), "=r"(r2), "=r"(r3) : "r"(addr));
}

#define GBM 128
#define GBN 128
#define GBK 32
#define RS2 20
#define STG (128 * RS2)
#define STG4 (STG * 4)
#define GEMM_SMEM (6 * STG4)        // 61440 bytes

__device__ __forceinline__ void epi_store(__nv_bfloat16* __restrict__ qb,
                                          __nv_bfloat16* __restrict__ kv,
                                          float* __restrict__ skip,
                                          int r, int c, float2 o) {
    if (c < OFF_K) {
        *(__nv_bfloat162*)(qb + (size_t)r * QB_W + c) = __float22bfloat162_rn(o);
    } else if (c < OFF_S) {
        bool isk = c < OFF_V;
        int ch = isk ? (c - OFF_K) : (c - OFF_V);
        int head = ch >> 7, within = ch & 127;
        int slot = head * 256 + (within >> 2) * 8 + (within & 3) + (isk ? 0 : 4);
        *(__nv_bfloat162*)(kv + (size_t)r * KV_W + slot) = __float22bfloat162_rn(o);
    } else if (c < NREAL) {
        *(float2*)(skip + (size_t)r * CC + (c - OFF_S)) = o;
    }
}

template<int NITER>
__global__ __launch_bounds__(256, 2)
void gemm_bf16_kernel(const __nv_bfloat16* __restrict__ A, const __nv_bfloat16* __restrict__ Bt,
                      const float* __restrict__ bias,
                      __nv_bfloat16* __restrict__ qb, __nv_bfloat16* __restrict__ kv,
                      float* __restrict__ skip, int M, int K) {
    extern __shared__ uint32_t smem[];
    uint32_t sbase = (uint32_t)__cvta_generic_to_shared(smem);

    int bm = blockIdx.y * GBM;
    int bn = blockIdx.x * GBN;
    int tid = threadIdx.x;
    int wid = tid >> 5, lane = tid & 31;
    int wm = (wid >> 2) * 64;
    int wn = (wid & 3) * 32;
    int gid = lane >> 2, tig = lane & 3;

    float acc[4][4][4];
    #pragma unroll
    for (int i = 0; i < 4; i++)
        #pragma unroll
        for (int j = 0; j < 4; j++)
            #pragma unroll
            for (int q = 0; q < 4; q++) acc[i][j][q] = 0.f;

    // cp.async loaders
    int lr = tid >> 1, lp = tid & 1;
    int rsafe = min(bm + lr, M - 1);
    const __nv_bfloat16* aPtr = A + (size_t)rsafe * K + lp * 16;
    const __nv_bfloat16* bPtr = Bt + (size_t)(bn + lr) * K + lp * 16;
    uint32_t aD = sbase + (lr * RS2 + lp * 8) * 4;
    uint32_t bD = sbase + 3 * STG4 + (lr * RS2 + lp * 8) * 4;

    // ldmatrix per-lane row/col mapping
    int l8 = lane & 7;
    int rowA = l8 + ((lane >> 3) & 1) * 8;
    int colA = (lane >> 4) * 4;
    int rowB = l8 + (lane >> 4) * 8;
    int colB = ((lane >> 3) & 1) * 4;

    // prologue: stages 0 and 1
    cp16(aD, aPtr);            cp16(aD + 16, aPtr + 8);
    cp16(bD, bPtr);            cp16(bD + 16, bPtr + 8);
    asm volatile("cp.async.commit_group;");
    if (NITER > 1) {
        cp16(aD + STG4, aPtr + 32);      cp16(aD + STG4 + 16, aPtr + 40);
        cp16(bD + STG4, bPtr + 32);      cp16(bD + STG4 + 16, bPtr + 40);
    }
    asm volatile("cp.async.commit_group;");

    #pragma unroll
    for (int it = 0; it < NITER; it++) {
        asm volatile("cp.async.wait_group 1;");
        __syncthreads();
        if (it + 2 < NITER) {
            int s = (it + 2) % 3;
            int kEl = (it + 2) * GBK;
            cp16(aD + s * STG4, aPtr + kEl);      cp16(aD + s * STG4 + 16, aPtr + kEl + 8);
            cp16(bD + s * STG4, bPtr + kEl);      cp16(bD + s * STG4 + 16, bPtr + kEl + 8);
        }
        asm volatile("cp.async.commit_group;");

        uint32_t sA = sbase + (it % 3) * STG4;
        uint32_t sB = sbase + 3 * STG4 + (it % 3) * STG4;
        #pragma unroll
        for (int kk2 = 0; kk2 < 16; kk2 += 8) {
            uint32_t af[4][4], bf[4][2];
            #pragma unroll
            for (int i = 0; i < 4; i++)
                ldsm4(af[i][0], af[i][1], af[i][2], af[i][3],
                      sA + ((wm + i * 16 + rowA) * RS2 + colA + kk2) * 4);
            #pragma unroll
            for (int j = 0; j < 4; j += 2)
                ldsm4(bf[j][0], bf[j][1], bf[j + 1][0], bf[j + 1][1],
                      sB + ((wn + j * 8 + rowB) * RS2 + colB + kk2) * 4);
            #pragma unroll
            for (int i = 0; i < 4; i++)
                #pragma unroll
                for (int j = 0; j < 4; j++)
                    mma_bf16(acc[i][j], af[i], bf[j]);
        }
    }

    #pragma unroll
    for (int i = 0; i < 4; i++) {
        int r0 = bm + wm + i * 16 + gid;
        #pragma unroll
        for (int j = 0; j < 4; j++) {
            int c = bn + wn + j * 8 + tig * 2;
            float2 bb = *(const float2*)(bias + c);
            if (r0 < M)
                epi_store(qb, kv, skip, r0, c,
                          make_float2(acc[i][j][0] + bb.x, acc[i][j][1] + bb.y));
            if (r0 + 8 < M)
                epi_store(qb, kv, skip, r0 + 8, c,
                          make_float2(acc[i][j][2] + bb.x, acc[i][j][3] + bb.y));
        }
    }
}

// ---------------- fused attention: batch-8 staged loads + ILP2 softmax ----------------
__global__ __launch_bounds__(256)
void attn_fused_kernel(const __nv_bfloat16* __restrict__ qb, const __nv_bfloat16* __restrict__ kv,
                       const int* __restrict__ rowptr, const int* __restrict__ col,
                       const float* __restrict__ skip, const float* __restrict__ Wb,
                       const float* __restrict__ gam, const float* __restrict__ bet,
                       const __nv_bfloat16* __restrict__ res, __nv_bfloat16* __restrict__ out) {
    __shared__ float sm[HH * CC + CC];
    int node = blockIdx.x;
    int wid  = threadIdx.x >> 5;
    int lane = threadIdx.x & 31;
    const float scale = 0.0883883476483184f; // 1/sqrt(128)

    uint2 qr = *(const uint2*)(qb + (size_t)node * QB_W + wid * CC + lane * 4);
    float2 qa = __bfloat1622float2(*(const __nv_bfloat162*)&qr.x);
    float2 qc = __bfloat1622float2(*(const __nv_bfloat162*)&qr.y);
    int e0 = rowptr[node], e1 = rowptr[node + 1];
    size_t off = (size_t)wid * 256 + lane * 8;

    float m0 = -1e30f, den0 = 0.f, m1 = -1e30f, den1 = 0.f;
    float4 a0 = make_float4(0.f, 0.f, 0.f, 0.f);
    float4 a1 = make_float4(0.f, 0.f, 0.f, 0.f);

    int e = e0;
    while (e < e1) {
        int cnt = e1 - e;
        if (cnt > 8) cnt = 8;
        // stage all kv loads for this batch (typ. the whole node: mean deg = 8)
        uint4 p[8];
        {
            int sfb = col[e];           // fallback index for unused slots (valid address)
            #pragma unroll
            for (int u = 0; u < 8; u++) {
                int s = (u < cnt) ? col[e + u] : sfb;
                p[u] = *(const uint4*)(kv + (size_t)s * KV_W + off);
            }
        }
        // process pairs through dual online-softmax states (R9 structure)
        #pragma unroll
        for (int u = 0; u < 8; u += 2) {
            if (u >= cnt) break;                         // uniform
            bool two = (u + 1 < cnt);
            float2 k0a = __bfloat1622float2(*(const __nv_bfloat162*)&p[u].x);
            float2 k0b = __bfloat1622float2(*(const __nv_bfloat162*)&p[u].y);
            float2 k1a = __bfloat1622float2(*(const __nv_bfloat162*)&p[u + 1].x);
            float2 k1b = __bfloat1622float2(*(const __nv_bfloat162*)&p[u + 1].y);
            float d0 = qa.x * k0a.x + qa.y * k0a.y + qc.x * k0b.x + qc.y * k0b.y;
            float d1 = qa.x * k1a.x + qa.y * k1a.y + qc.x * k1b.x + qc.y * k1b.y;
            #pragma unroll
            for (int o = 16; o; o >>= 1) {
                d0 += __shfl_xor_sync(0xffffffffu, d0, o);
                d1 += __shfl_xor_sync(0xffffffffu, d1, o);
            }
            float2 v0a = __bfloat1622float2(*(const __nv_bfloat162*)&p[u].z);
            float2 v0b = __bfloat1622float2(*(const __nv_bfloat162*)&p[u].w);
            {
                float lg = d0 * scale;
                float mn = fmaxf(m0, lg);
                float cr = __expf(m0 - mn), pp = __expf(lg - mn);
                den0 = den0 * cr + pp;
                a0.x = a0.x * cr + pp * v0a.x; a0.y = a0.y * cr + pp * v0a.y;
                a0.z = a0.z * cr + pp * v0b.x; a0.w = a0.w * cr + pp * v0b.y;
                m0 = mn;
            }
            if (two) {
                float2 v1a = __bfloat1622float2(*(const __nv_bfloat162*)&p[u + 1].z);
                float2 v1b = __bfloat1622float2(*(const __nv_bfloat162*)&p[u + 1].w);
                float lg = d1 * scale;
                float mn = fmaxf(m1, lg);
                float cr = __expf(m1 - mn), pp = __expf(lg - mn);
                den1 = den1 * cr + pp;
                a1.x = a1.x * cr + pp * v1a.x; a1.y = a1.y * cr + pp * v1a.y;
                a1.z = a1.z * cr + pp * v1b.x; a1.w = a1.w * cr + pp * v1b.y;
                m1 = mn;
            }
        }
        e += cnt;
    }
    float M = fmaxf(m0, m1);
    float c0 = __expf(m0 - M), c1 = __expf(m1 - M);
    float den = den0 * c0 + den1 * c1;
    float4 acc;
    acc.x = a0.x * c0 + a1.x * c1;
    acc.y = a0.y * c0 + a1.y * c1;
    acc.z = a0.z * c0 + a1.z * c1;
    acc.w = a0.w * c0 + a1.w * c1;

    float inv = 1.f / (den + 1e-16f);
    sm[wid * CC + lane * 4 + 0] = acc.x * inv;
    sm[wid * CC + lane * 4 + 1] = acc.y * inv;
    sm[wid * CC + lane * 4 + 2] = acc.z * inv;
    sm[wid * CC + lane * 4 + 3] = acc.w * inv;
    __syncthreads();

    if (threadIdx.x < CC) {
        float s = 0.f;
        #pragma unroll
        for (int h = 0; h < HH; h++) s += sm[h * CC + threadIdx.x];
        sm[HH * CC + threadIdx.x] = s * 0.125f;
    }
    __syncthreads();

    if (threadIdx.x < 32) {
        int c = threadIdx.x * 4;
        float4 a  = *(float4*)&sm[HH * CC + c];
        float4 xr = *(const float4*)(skip + (size_t)node * CC + c);
        float4 w0 = *(const float4*)(Wb + c);
        float4 w1 = *(const float4*)(Wb + 128 + c);
        float4 w2 = *(const float4*)(Wb + 256 + c);

        float t = a.x * w0.x + a.y * w0.y + a.z * w0.z + a.w * w0.w
                + xr.x * w1.x + xr.y * w1.y + xr.z * w1.z + xr.w * w1.w
                + (a.x - xr.x) * w2.x + (a.y - xr.y) * w2.y
                + (a.z - xr.z) * w2.z + (a.w - xr.w) * w2.w;
        #pragma unroll
        for (int o = 16; o; o >>= 1) t += __shfl_xor_sync(0xffffffffu, t, o);
        float beta = 1.f / (1.f + __expf(-t));

        float4 y;
        y.x = beta * xr.x + (1.f - beta) * a.x;
        y.y = beta * xr.y + (1.f - beta) * a.y;
        y.z = beta * xr.z + (1.f - beta) * a.z;
        y.w = beta * xr.w + (1.f - beta) * a.w;
        if (res) {
            uint2 rr = *(const uint2*)(res + (size_t)node * CC + c);
            float2 r0 = __bfloat1622float2(*(const __nv_bfloat162*)&rr.x);
            float2 r1 = __bfloat1622float2(*(const __nv_bfloat162*)&rr.y);
            y.x += r0.x; y.y += r0.y; y.z += r1.x; y.w += r1.y;
        }
        float s = y.x + y.y + y.z + y.w;
        #pragma unroll
        for (int o = 16; o; o >>= 1) s += __shfl_xor_sync(0xffffffffu, s, o);
        float mu = s * (1.f / 128.f);
        float dx0 = y.x - mu, dx1 = y.y - mu, dx2 = y.z - mu, dx3 = y.w - mu;
        float q = dx0 * dx0 + dx1 * dx1 + dx2 * dx2 + dx3 * dx3;
        #pragma unroll
        for (int o = 16; o; o >>= 1) q += __shfl_xor_sync(0xffffffffu, q, o);
        float rstd = rsqrtf(q * (1.f / 128.f) + 1e-5f);
        float4 gg = *(const float4*)(gam + c);
        float4 bb = *(const float4*)(bet + c);
        float2 o0, o1;
        o0.x = fmaxf(dx0 * rstd * gg.x + bb.x, 0.f);
        o0.y = fmaxf(dx1 * rstd * gg.y + bb.y, 0.f);
        o1.x = fmaxf(dx2 * rstd * gg.z + bb.z, 0.f);
        o1.y = fmaxf(dx3 * rstd * gg.w + bb.w, 0.f);
        uint2 ow;
        *(__nv_bfloat162*)&ow.x = __float22bfloat162_rn(o0);
        *(__nv_bfloat162*)&ow.y = __float22bfloat162_rn(o1);
        *(uint2*)(out + (size_t)node * CC + c) = ow;
    }
}

// ---------------- pooling (batch sorted) ----------------
__global__ __launch_bounds__(128)
void pool_kernel(const __nv_bfloat16* __restrict__ h, const int* __restrict__ batch,
                 float* __restrict__ psum, float* __restrict__ cnt, int N) {
    int c = threadIdx.x;
    int n0 = blockIdx.x * 64;
    int n1 = min(n0 + 64, N);
    int cur = batch[n0];
    float s = 0.f;
    float k = 0.f;
    for (int n = n0; n < n1; n++) {
        int b = batch[n];
        if (b != cur) {
            atomicAdd(&psum[cur * CC + c], s);
            if (c == 0) atomicAdd(&cnt[cur], k);
            s = 0.f; k = 0.f; cur = b;
        }
        s += __bfloat162float(h[(size_t)n * CC + c]);
        k += 1.f;
    }
    atomicAdd(&psum[cur * CC + c], s);
    if (c == 0) atomicAdd(&cnt[cur], k);
}

// ---------------- classifier ----------------
__global__ void cls_kernel(const float* __restrict__ psum, const float* __restrict__ cnt,
                           const float* __restrict__ Wc1, const float* __restrict__ bc1,
                           const float* __restrict__ Wc2, const float* __restrict__ bc2,
                           float* __restrict__ out) {
    int g = threadIdx.x;
    if (g >= NG) return;
    float invc = 1.f / fmaxf(cnt[g], 1.f);
    float pooled[CC];
    #pragma unroll 8
    for (int c = 0; c < CC; c++) pooled[c] = psum[g * CC + c] * invc;
    float r = bc2[0];
    for (int j = 0; j < 64; j++) {
        float z = bc1[j];
        #pragma unroll 8
        for (int c = 0; c < CC; c++) z += pooled[c] * Wc1[c * 64 + j];
        r += fmaxf(z, 0.f) * Wc2[j];
    }
    out[g] = r;
}

// ---------------- launch ----------------
extern "C" void kernel_launch(void* const* d_in, const int* in_sizes, int n_in,
                              void* d_out, int out_size) {
    const int N = NN, E = EE;
    const int*   x     = (const int*)d_in[0];
    const int*   ei    = (const int*)d_in[1];
    const int*   src   = ei;
    const int*   dst   = ei + E;
    const int*   batch = (const int*)d_in[2];
    const float* emb   = (const float*)d_in[3];

    const float *Wq0 = (const float*)d_in[4],  *bq0 = (const float*)d_in[5];
    const float *Wk0 = (const float*)d_in[6],  *bk0 = (const float*)d_in[7];
    const float *Wv0 = (const float*)d_in[8],  *bv0 = (const float*)d_in[9];
    const float *Ws0 = (const float*)d_in[10], *bs0 = (const float*)d_in[11];
    const float *Wb0 = (const float*)d_in[12];
    const float *g0  = (const float*)d_in[13], *be0 = (const float*)d_in[14];
    const float *Wq1 = (const float*)d_in[15], *bq1 = (const float*)d_in[16];
    const float *Wk1 = (const float*)d_in[17], *bk1 = (const float*)d_in[18];
    const float *Wv1 = (const float*)d_in[19], *bv1 = (const float*)d_in[20];
    const float *Ws1 = (const float*)d_in[21], *bs1 = (const float*)d_in[22];
    const float *Wb1 = (const float*)d_in[23];
    const float *g1  = (const float*)d_in[24], *be1 = (const float*)d_in[25];
    const float *Wc1 = (const float*)d_in[26], *bc1 = (const float*)d_in[27];
    const float *Wc2 = (const float*)d_in[28], *bc2 = (const float*)d_in[29];

    __nv_bfloat16 *hb, *qbb, *kv, *h1, *h2, *Wt;
    float *skip, *bcat, *pool, *cnt;
    int *deg, *rowptr, *wofs, *col, *bsum, *bsum2;
    cudaGetSymbolAddress((void**)&hb,     g_hb);
    cudaGetSymbolAddress((void**)&qbb,    g_qb);
    cudaGetSymbolAddress((void**)&kv,     g_kv);
    cudaGetSymbolAddress((void**)&skip,   g_skip);
    cudaGetSymbolAddress((void**)&h1,     g_h1);
    cudaGetSymbolAddress((void**)&h2,     g_h2);
    cudaGetSymbolAddress((void**)&Wt,     g_Wt);
    cudaGetSymbolAddress((void**)&bcat,   g_bcat);
    cudaGetSymbolAddress((void**)&pool,   g_pool);
    cudaGetSymbolAddress((void**)&cnt,    g_cnt);
    cudaGetSymbolAddress((void**)&deg,    g_deg);
    cudaGetSymbolAddress((void**)&rowptr, g_rowptr);
    cudaGetSymbolAddress((void**)&wofs,   g_wofs);
    cudaGetSymbolAddress((void**)&col,    g_col);
    cudaGetSymbolAddress((void**)&bsum,   g_bsum);
    cudaGetSymbolAddress((void**)&bsum2,  g_bsum2);

    cudaFuncSetAttribute(gemm_bf16_kernel<8>, cudaFuncAttributeMaxDynamicSharedMemorySize,
                         GEMM_SMEM);
    cudaFuncSetAttribute(gemm_bf16_kernel<4>, cudaFuncAttributeMaxDynamicSharedMemorySize,
                         GEMM_SMEM);

    const int NB = (N + 255) / 256;
    dim3 ggrid(NOUT / GBN, (N + GBM - 1) / GBM);   // (26, 391)
    dim3 pgrid(NOUT / 32, 256 / 32);
    dim3 pgrid1(NOUT / 32, 128 / 32);
    dim3 pthr(32, 8);

    // launches ordered so gemm #0 is my 5th launch (profiled slot)
    cudaMemsetAsync(deg, 0, N * sizeof(int));                                   // 1
    hist_kernel<<<(E + 255) / 256, 256>>>(dst, deg, E);                         // 2
    embed_kernel<<<(N * 32 + 255) / 256, 256>>>(x, emb, hb, N);                 // 3
    pack_kernel<<<pgrid, pthr>>>(Wq0, Wk0, Wv0, Ws0, bq0, bk0, bv0, bs0,
                                 Wt, bcat, 256);                                // 4
    gemm_bf16_kernel<8><<<ggrid, 256, GEMM_SMEM>>>(hb, Wt, bcat, qbb, kv, skip,
                                                   N, 256);                     // 5 <- profiled
    scan_block_kernel<<<NB, 256>>>(deg, rowptr, bsum, N);                       // 6
    scan_bsum_kernel<<<1, 256>>>(bsum, bsum2, NB);                              // 7
    scan_add_kernel<<<NB, 256>>>(rowptr, bsum2, wofs, N);                       // 8
    scatter_kernel<<<(E + 255) / 256, 256>>>(src, dst, wofs, col, E);           // 9
    attn_fused_kernel<<<N, 256>>>(qbb, kv, rowptr, col, skip, Wb0, g0, be0,
                                  (const __nv_bfloat16*)nullptr, h1);           // 10

    pack_kernel<<<pgrid1, pthr>>>(Wq1, Wk1, Wv1, Ws1, bq1, bk1, bv1, bs1,
                                  Wt, bcat, 128);                               // 11
    gemm_bf16_kernel<4><<<ggrid, 256, GEMM_SMEM>>>(h1, Wt, bcat, qbb, kv, skip,
                                                   N, 128);                     // 12
    attn_fused_kernel<<<N, 256>>>(qbb, kv, rowptr, col, skip, Wb1, g1, be1,
                                  h1, h2);                                      // 13

    cudaMemsetAsync(pool, 0, NG * CC * sizeof(float));
    cudaMemsetAsync(cnt, 0, NG * sizeof(float));
    pool_kernel<<<(N + 63) / 64, 128>>>(h2, batch, pool, cnt, N);
    cls_kernel<<<1, 64>>>(pool, cnt, Wc1, bc1, Wc2, bc2, (float*)d_out);
}

// round 14
// speedup vs baseline: 1.1436x; 1.1436x over previous
#include <cuda_runtime.h>
#include <cuda_bf16.h>
#include <math.h>
#include <stdint.h>

// ---------------- problem constants ----------------
#define NN 50000
#define EE 400000
#define HH 8
#define CC 128
#define EMB 256
#define NG 64
#define NOUT 3328
#define NREAL 3200
#define OFF_K 1024
#define OFF_V 2048
#define OFF_S 3072
#define KV_W 2048
#define QB_W 1024

// ---------------- scratch ----------------
__device__ __nv_bfloat16 g_hb[(size_t)NN * EMB];
__device__ __nv_bfloat16 g_qb[(size_t)NN * QB_W];
__device__ __nv_bfloat16 g_kv[(size_t)NN * KV_W];
__device__ float g_skip[(size_t)NN * CC];
__device__ __nv_bfloat16 g_h1[(size_t)NN * CC];
__device__ __nv_bfloat16 g_h2[(size_t)NN * CC];
__device__ __nv_bfloat16 g_Wt[(size_t)NOUT * EMB];
__device__ float g_bcat[NOUT];
__device__ float g_pool[NG * CC];
__device__ float g_cnt[NG];
__device__ int   g_deg[NN];
__device__ int   g_rowptr[NN + 1];
__device__ int   g_wofs[NN + 1];
__device__ int   g_col[EE];
__device__ int   g_bsum[256];
__device__ int   g_bsum2[256];

// ---------------- CSR build ----------------
__global__ void hist_kernel(const int* __restrict__ dst, int* __restrict__ deg, int E) {
    int e = blockIdx.x * blockDim.x + threadIdx.x;
    if (e < E) atomicAdd(&deg[dst[e]], 1);
}

__global__ void scan_block_kernel(const int* __restrict__ deg, int* __restrict__ rowptr,
                                  int* __restrict__ bsum, int n) {
    __shared__ int s[256];
    int i = blockIdx.x * 256 + threadIdx.x;
    int v = (i < n) ? deg[i] : 0;
    s[threadIdx.x] = v;
    __syncthreads();
    #pragma unroll
    for (int off = 1; off < 256; off <<= 1) {
        int t = (threadIdx.x >= off) ? s[threadIdx.x - off] : 0;
        __syncthreads();
        s[threadIdx.x] += t;
        __syncthreads();
    }
    if (i < n) rowptr[i + 1] = s[threadIdx.x];
    if (threadIdx.x == 255) bsum[blockIdx.x] = s[255];
}

__global__ void scan_bsum_kernel(const int* __restrict__ bsum, int* __restrict__ bsum2, int nb) {
    __shared__ int s[256];
    int t = threadIdx.x;
    int v = (t < nb) ? bsum[t] : 0;
    s[t] = v;
    __syncthreads();
    #pragma unroll
    for (int off = 1; off < 256; off <<= 1) {
        int x = (t >= off) ? s[t - off] : 0;
        __syncthreads();
        s[t] += x;
        __syncthreads();
    }
    if (t < nb) bsum2[t] = s[t] - v;   // exclusive
}

__global__ void scan_add_kernel(int* __restrict__ rowptr, const int* __restrict__ bsum2,
                                int* __restrict__ wofs, int n) {
    int i = blockIdx.x * 256 + threadIdx.x;
    if (i < n) {
        int v = rowptr[i + 1] + bsum2[blockIdx.x];
        rowptr[i + 1] = v;
        wofs[i + 1] = v;
    }
    if (i == 0) { rowptr[0] = 0; wofs[0] = 0; }
}

__global__ void scatter_kernel(const int* __restrict__ src, const int* __restrict__ dst,
                               int* __restrict__ wofs, int* __restrict__ col, int E) {
    int e = blockIdx.x * blockDim.x + threadIdx.x;
    if (e < E) {
        int p = atomicAdd(&wofs[dst[e]], 1);
        col[p] = src[e];
    }
}

// ---------------- embedding gather ----------------
__global__ void embed_kernel(const int* __restrict__ x, const float* __restrict__ emb,
                             __nv_bfloat16* __restrict__ hb, int N) {
    int idx = blockIdx.x * blockDim.x + threadIdx.x;
    if (idx >= N * 32) return;
    int n  = idx >> 5;
    int g8 = (idx & 31) << 3;
    const float* p = emb + (size_t)x[n] * EMB + g8;
    float4 a = *(const float4*)p;
    float4 b = *(const float4*)(p + 4);
    __nv_bfloat162 o[4];
    o[0] = __float22bfloat162_rn(make_float2(a.x, a.y));
    o[1] = __float22bfloat162_rn(make_float2(a.z, a.w));
    o[2] = __float22bfloat162_rn(make_float2(b.x, b.y));
    o[3] = __float22bfloat162_rn(make_float2(b.z, b.w));
    *(uint4*)(hb + (size_t)n * EMB + g8) = *(uint4*)o;
}

// ---------------- weight pack: tiled transpose ----------------
__global__ void pack_kernel(const float* __restrict__ Wq, const float* __restrict__ Wk,
                            const float* __restrict__ Wv, const float* __restrict__ Ws,
                            const float* __restrict__ bq, const float* __restrict__ bk,
                            const float* __restrict__ bv, const float* __restrict__ bs,
                            __nv_bfloat16* __restrict__ Wt, float* __restrict__ bcat, int K) {
    __shared__ float t[32][33];
    int n0 = blockIdx.x * 32, k0 = blockIdx.y * 32;
    int tx = threadIdx.x, ty = threadIdx.y;
    #pragma unroll
    for (int i = 0; i < 4; i++) {
        int k = k0 + ty + i * 8;
        int n = n0 + tx;
        float v;
        if (n < 1024)       v = Wq[k * 1024 + n];
        else if (n < 2048)  v = Wk[k * 1024 + (n - 1024)];
        else if (n < 3072)  v = Wv[k * 1024 + (n - 2048)];
        else if (n < NREAL) v = Ws[k * 128  + (n - 3072)];
        else                v = 0.f;
        t[ty + i * 8][tx] = v;
    }
    if (k0 == 0 && ty == 0) {
        int n = n0 + tx;
        float b;
        if (n < 1024)       b = bq[n];
        else if (n < 2048)  b = bk[n - 1024];
        else if (n < 3072)  b = bv[n - 2048];
        else if (n < NREAL) b = bs[n - 3072];
        else                b = 0.f;
        bcat[n] = b;
    }
    __syncthreads();
    #pragma unroll
    for (int i = 0; i < 4; i++) {
        int n = n0 + ty + i * 8;
        int k = k0 + tx;
        Wt[(size_t)n * K + k] = __float2bfloat16(t[tx][ty + i * 8]);
    }
}

// ---------------- bf16 GEMM: 128x128x32, 4-stage cp.async ring, ldmatrix, 2 CTAs/SM ----------------
__device__ __forceinline__ void mma_bf16(float* c, const uint32_t* a, const uint32_t* b) {
    asm volatile(
        "mma.sync.aligned.m16n8k16.row.col.f32.bf16.bf16.f32 "
        "{%0,%1,%2,%3}, {%4,%5,%6,%7}, {%8,%9}, {%0,%1,%2,%3};"
        : "+f"(c[0]), "+f"(c[1]), "+f"(c[2]), "+f"(c[3])
        : "r"(a[0]), "r"(a[1]), "r"(a[2]), "r"(a[3]), "r"(b[0]), "r"(b[1]));
}

__device__ __forceinline__ void cp16(uint32_t dst, const void* src) {
    asm volatile("cp.async.cg.shared.global [%0], [%1], 16;" :: "r"(dst), "l"(src));
}

__device__ __forceinline__ void ldsm4(uint32_t& r0, uint32_t& r1, uint32_t& r2, uint32_t& r3,
                                      uint32_t addr) {
    asm volatile("ldmatrix.sync.aligned.m8n8.x4.shared.b16 {%0,%1,%2,%3}, [%4];"
        : "=r"(r0), "=r"(r1), "=r"(r2), "=r"(r3) : "r"(addr));
}

#define GBM 128
#define GBN 128
#define GBK 32
#define RS2 20
#define STG (128 * RS2)
#define STG4 (STG * 4)
#define NSTAGE 4
#define GEMM_SMEM (2 * NSTAGE * STG4)   // 81920 bytes

__device__ __forceinline__ void epi_store(__nv_bfloat16* __restrict__ qb,
                                          __nv_bfloat16* __restrict__ kv,
                                          float* __restrict__ skip,
                                          int r, int c, float2 o) {
    if (c < OFF_K) {
        *(__nv_bfloat162*)(qb + (size_t)r * QB_W + c) = __float22bfloat162_rn(o);
    } else if (c < OFF_S) {
        bool isk = c < OFF_V;
        int ch = isk ? (c - OFF_K) : (c - OFF_V);
        int head = ch >> 7, within = ch & 127;
        int slot = head * 256 + (within >> 2) * 8 + (within & 3) + (isk ? 0 : 4);
        *(__nv_bfloat162*)(kv + (size_t)r * KV_W + slot) = __float22bfloat162_rn(o);
    } else if (c < NREAL) {
        *(float2*)(skip + (size_t)r * CC + (c - OFF_S)) = o;
    }
}

template<int NITER>
__global__ __launch_bounds__(256, 2)
void gemm_bf16_kernel(const __nv_bfloat16* __restrict__ A, const __nv_bfloat16* __restrict__ Bt,
                      const float* __restrict__ bias,
                      __nv_bfloat16* __restrict__ qb, __nv_bfloat16* __restrict__ kv,
                      float* __restrict__ skip, int M, int K) {
    extern __shared__ uint32_t smem[];
    uint32_t sbase = (uint32_t)__cvta_generic_to_shared(smem);

    int bm = blockIdx.y * GBM;
    int bn = blockIdx.x * GBN;
    int tid = threadIdx.x;
    int wid = tid >> 5, lane = tid & 31;
    int wm = (wid >> 2) * 64;
    int wn = (wid & 3) * 32;
    int gid = lane >> 2, tig = lane & 3;

    float acc[4][4][4];
    #pragma unroll
    for (int i = 0; i < 4; i++)
        #pragma unroll
        for (int j = 0; j < 4; j++)
            #pragma unroll
            for (int q = 0; q < 4; q++) acc[i][j][q] = 0.f;

    // cp.async loaders
    int lr = tid >> 1, lp = tid & 1;
    int rsafe = min(bm + lr, M - 1);
    const __nv_bfloat16* aPtr = A + (size_t)rsafe * K + lp * 16;
    const __nv_bfloat16* bPtr = Bt + (size_t)(bn + lr) * K + lp * 16;
    uint32_t aD = sbase + (lr * RS2 + lp * 8) * 4;
    uint32_t bD = sbase + NSTAGE * STG4 + (lr * RS2 + lp * 8) * 4;

    // ldmatrix per-lane row/col mapping
    int l8 = lane & 7;
    int rowA = l8 + ((lane >> 3) & 1) * 8;
    int colA = (lane >> 4) * 4;
    int rowB = l8 + (lane >> 4) * 8;
    int colB = ((lane >> 3) & 1) * 4;

    // prologue: fill stages 0..2 (3 committed groups)
    #pragma unroll
    for (int s = 0; s < 3; s++) {
        if (s < NITER) {
            int kEl = s * GBK;
            cp16(aD + s * STG4, aPtr + kEl);      cp16(aD + s * STG4 + 16, aPtr + kEl + 8);
            cp16(bD + s * STG4, bPtr + kEl);      cp16(bD + s * STG4 + 16, bPtr + kEl + 8);
        }
        asm volatile("cp.async.commit_group;");
    }

    #pragma unroll
    for (int it = 0; it < NITER; it++) {
        asm volatile("cp.async.wait_group 2;");
        __syncthreads();
        if (it + 3 < NITER) {
            int s = (it + 3) % NSTAGE;
            int kEl = (it + 3) * GBK;
            cp16(aD + s * STG4, aPtr + kEl);      cp16(aD + s * STG4 + 16, aPtr + kEl + 8);
            cp16(bD + s * STG4, bPtr + kEl);      cp16(bD + s * STG4 + 16, bPtr + kEl + 8);
        }
        asm volatile("cp.async.commit_group;");

        uint32_t sA = sbase + (it % NSTAGE) * STG4;
        uint32_t sB = sbase + NSTAGE * STG4 + (it % NSTAGE) * STG4;
        #pragma unroll
        for (int kk2 = 0; kk2 < 16; kk2 += 8) {
            uint32_t af[4][4], bf[4][2];
            #pragma unroll
            for (int i = 0; i < 4; i++)
                ldsm4(af[i][0], af[i][1], af[i][2], af[i][3],
                      sA + ((wm + i * 16 + rowA) * RS2 + colA + kk2) * 4);
            #pragma unroll
            for (int j = 0; j < 4; j += 2)
                ldsm4(bf[j][0], bf[j][1], bf[j + 1][0], bf[j + 1][1],
                      sB + ((wn + j * 8 + rowB) * RS2 + colB + kk2) * 4);
            #pragma unroll
            for (int i = 0; i < 4; i++)
                #pragma unroll
                for (int j = 0; j < 4; j++)
                    mma_bf16(acc[i][j], af[i], bf[j]);
        }
    }

    #pragma unroll
    for (int i = 0; i < 4; i++) {
        int r0 = bm + wm + i * 16 + gid;
        #pragma unroll
        for (int j = 0; j < 4; j++) {
            int c = bn + wn + j * 8 + tig * 2;
            float2 bb = *(const float2*)(bias + c);
            if (r0 < M)
                epi_store(qb, kv, skip, r0, c,
                          make_float2(acc[i][j][0] + bb.x, acc[i][j][1] + bb.y));
            if (r0 + 8 < M)
                epi_store(qb, kv, skip, r0 + 8, c,
                          make_float2(acc[i][j][2] + bb.x, acc[i][j][3] + bb.y));
        }
    }
}

// ---------------- fused attention + beta-gate + LayerNorm + ReLU (ILP x2, R9 exact) ----------------
__global__ __launch_bounds__(256)
void attn_fused_kernel(const __nv_bfloat16* __restrict__ qb, const __nv_bfloat16* __restrict__ kv,
                       const int* __restrict__ rowptr, const int* __restrict__ col,
                       const float* __restrict__ skip, const float* __restrict__ Wb,
                       const float* __restrict__ gam, const float* __restrict__ bet,
                       const __nv_bfloat16* __restrict__ res, __nv_bfloat16* __restrict__ out) {
    __shared__ float sm[HH * CC + CC];
    int node = blockIdx.x;
    int wid  = threadIdx.x >> 5;
    int lane = threadIdx.x & 31;
    const float scale = 0.0883883476483184f; // 1/sqrt(128)

    uint2 qr = *(const uint2*)(qb + (size_t)node * QB_W + wid * CC + lane * 4);
    float2 qa = __bfloat1622float2(*(const __nv_bfloat162*)&qr.x);
    float2 qc = __bfloat1622float2(*(const __nv_bfloat162*)&qr.y);
    int e0 = rowptr[node], e1 = rowptr[node + 1];
    size_t off = (size_t)wid * 256 + lane * 8;

    float m0 = -1e30f, den0 = 0.f, m1 = -1e30f, den1 = 0.f;
    float4 a0 = make_float4(0.f, 0.f, 0.f, 0.f);
    float4 a1 = make_float4(0.f, 0.f, 0.f, 0.f);

    int e = e0;
    for (; e + 1 < e1; e += 2) {
        int s0 = col[e], s1 = col[e + 1];
        uint4 p0 = *(const uint4*)(kv + (size_t)s0 * KV_W + off);
        uint4 p1 = *(const uint4*)(kv + (size_t)s1 * KV_W + off);
        float2 k0a = __bfloat1622float2(*(const __nv_bfloat162*)&p0.x);
        float2 k0b = __bfloat1622float2(*(const __nv_bfloat162*)&p0.y);
        float2 k1a = __bfloat1622float2(*(const __nv_bfloat162*)&p1.x);
        float2 k1b = __bfloat1622float2(*(const __nv_bfloat162*)&p1.y);
        float d0 = qa.x * k0a.x + qa.y * k0a.y + qc.x * k0b.x + qc.y * k0b.y;
        float d1 = qa.x * k1a.x + qa.y * k1a.y + qc.x * k1b.x + qc.y * k1b.y;
        #pragma unroll
        for (int o = 16; o; o >>= 1) {
            d0 += __shfl_xor_sync(0xffffffffu, d0, o);
            d1 += __shfl_xor_sync(0xffffffffu, d1, o);
        }
        float2 v0a = __bfloat1622float2(*(const __nv_bfloat162*)&p0.z);
        float2 v0b = __bfloat1622float2(*(const __nv_bfloat162*)&p0.w);
        float2 v1a = __bfloat1622float2(*(const __nv_bfloat162*)&p1.z);
        float2 v1b = __bfloat1622float2(*(const __nv_bfloat162*)&p1.w);
        {
            float lg = d0 * scale;
            float mn = fmaxf(m0, lg);
            float cr = __expf(m0 - mn), p = __expf(lg - mn);
            den0 = den0 * cr + p;
            a0.x = a0.x * cr + p * v0a.x; a0.y = a0.y * cr + p * v0a.y;
            a0.z = a0.z * cr + p * v0b.x; a0.w = a0.w * cr + p * v0b.y;
            m0 = mn;
        }
        {
            float lg = d1 * scale;
            float mn = fmaxf(m1, lg);
            float cr = __expf(m1 - mn), p = __expf(lg - mn);
            den1 = den1 * cr + p;
            a1.x = a1.x * cr + p * v1a.x; a1.y = a1.y * cr + p * v1a.y;
            a1.z = a1.z * cr + p * v1b.x; a1.w = a1.w * cr + p * v1b.y;
            m1 = mn;
        }
    }
    if (e < e1) {
        int s0 = col[e];
        uint4 p0 = *(const uint4*)(kv + (size_t)s0 * KV_W + off);
        float2 k0a = __bfloat1622float2(*(const __nv_bfloat162*)&p0.x);
        float2 k0b = __bfloat1622float2(*(const __nv_bfloat162*)&p0.y);
        float d0 = qa.x * k0a.x + qa.y * k0a.y + qc.x * k0b.x + qc.y * k0b.y;
        #pragma unroll
        for (int o = 16; o; o >>= 1) d0 += __shfl_xor_sync(0xffffffffu, d0, o);
        float2 v0a = __bfloat1622float2(*(const __nv_bfloat162*)&p0.z);
        float2 v0b = __bfloat1622float2(*(const __nv_bfloat162*)&p0.w);
        float lg = d0 * scale;
        float mn = fmaxf(m0, lg);
        float cr = __expf(m0 - mn), p = __expf(lg - mn);
        den0 = den0 * cr + p;
        a0.x = a0.x * cr + p * v0a.x; a0.y = a0.y * cr + p * v0a.y;
        a0.z = a0.z * cr + p * v0b.x; a0.w = a0.w * cr + p * v0b.y;
        m0 = mn;
    }
    float M = fmaxf(m0, m1);
    float c0 = __expf(m0 - M), c1 = __expf(m1 - M);
    float den = den0 * c0 + den1 * c1;
    float4 acc;
    acc.x = a0.x * c0 + a1.x * c1;
    acc.y = a0.y * c0 + a1.y * c1;
    acc.z = a0.z * c0 + a1.z * c1;
    acc.w = a0.w * c0 + a1.w * c1;

    float inv = 1.f / (den + 1e-16f);
    sm[wid * CC + lane * 4 + 0] = acc.x * inv;
    sm[wid * CC + lane * 4 + 1] = acc.y * inv;
    sm[wid * CC + lane * 4 + 2] = acc.z * inv;
    sm[wid * CC + lane * 4 + 3] = acc.w * inv;
    __syncthreads();

    if (threadIdx.x < CC) {
        float s = 0.f;
        #pragma unroll
        for (int h = 0; h < HH; h++) s += sm[h * CC + threadIdx.x];
        sm[HH * CC + threadIdx.x] = s * 0.125f;
    }
    __syncthreads();

    if (threadIdx.x < 32) {
        int c = threadIdx.x * 4;
        float4 a  = *(float4*)&sm[HH * CC + c];
        float4 xr = *(const float4*)(skip + (size_t)node * CC + c);
        float4 w0 = *(const float4*)(Wb + c);
        float4 w1 = *(const float4*)(Wb + 128 + c);
        float4 w2 = *(const float4*)(Wb + 256 + c);

        float t = a.x * w0.x + a.y * w0.y + a.z * w0.z + a.w * w0.w
                + xr.x * w1.x + xr.y * w1.y + xr.z * w1.z + xr.w * w1.w
                + (a.x - xr.x) * w2.x + (a.y - xr.y) * w2.y
                + (a.z - xr.z) * w2.z + (a.w - xr.w) * w2.w;
        #pragma unroll
        for (int o = 16; o; o >>= 1) t += __shfl_xor_sync(0xffffffffu, t, o);
        float beta = 1.f / (1.f + __expf(-t));

        float4 y;
        y.x = beta * xr.x + (1.f - beta) * a.x;
        y.y = beta * xr.y + (1.f - beta) * a.y;
        y.z = beta * xr.z + (1.f - beta) * a.z;
        y.w = beta * xr.w + (1.f - beta) * a.w;
        if (res) {
            uint2 rr = *(const uint2*)(res + (size_t)node * CC + c);
            float2 r0 = __bfloat1622float2(*(const __nv_bfloat162*)&rr.x);
            float2 r1 = __bfloat1622float2(*(const __nv_bfloat162*)&rr.y);
            y.x += r0.x; y.y += r0.y; y.z += r1.x; y.w += r1.y;
        }
        float s = y.x + y.y + y.z + y.w;
        #pragma unroll
        for (int o = 16; o; o >>= 1) s += __shfl_xor_sync(0xffffffffu, s, o);
        float mu = s * (1.f / 128.f);
        float dx0 = y.x - mu, dx1 = y.y - mu, dx2 = y.z - mu, dx3 = y.w - mu;
        float q = dx0 * dx0 + dx1 * dx1 + dx2 * dx2 + dx3 * dx3;
        #pragma unroll
        for (int o = 16; o; o >>= 1) q += __shfl_xor_sync(0xffffffffu, q, o);
        float rstd = rsqrtf(q * (1.f / 128.f) + 1e-5f);
        float4 gg = *(const float4*)(gam + c);
        float4 bb = *(const float4*)(bet + c);
        float2 o0, o1;
        o0.x = fmaxf(dx0 * rstd * gg.x + bb.x, 0.f);
        o0.y = fmaxf(dx1 * rstd * gg.y + bb.y, 0.f);
        o1.x = fmaxf(dx2 * rstd * gg.z + bb.z, 0.f);
        o1.y = fmaxf(dx3 * rstd * gg.w + bb.w, 0.f);
        uint2 ow;
        *(__nv_bfloat162*)&ow.x = __float22bfloat162_rn(o0);
        *(__nv_bfloat162*)&ow.y = __float22bfloat162_rn(o1);
        *(uint2*)(out + (size_t)node * CC + c) = ow;
    }
}

// ---------------- pooling (batch sorted) ----------------
__global__ __launch_bounds__(128)
void pool_kernel(const __nv_bfloat16* __restrict__ h, const int* __restrict__ batch,
                 float* __restrict__ psum, float* __restrict__ cnt, int N) {
    int c = threadIdx.x;
    int n0 = blockIdx.x * 64;
    int n1 = min(n0 + 64, N);
    int cur = batch[n0];
    float s = 0.f;
    float k = 0.f;
    for (int n = n0; n < n1; n++) {
        int b = batch[n];
        if (b != cur) {
            atomicAdd(&psum[cur * CC + c], s);
            if (c == 0) atomicAdd(&cnt[cur], k);
            s = 0.f; k = 0.f; cur = b;
        }
        s += __bfloat162float(h[(size_t)n * CC + c]);
        k += 1.f;
    }
    atomicAdd(&psum[cur * CC + c], s);
    if (c == 0) atomicAdd(&cnt[cur], k);
}

// ---------------- classifier ----------------
__global__ void cls_kernel(const float* __restrict__ psum, const float* __restrict__ cnt,
                           const float* __restrict__ Wc1, const float* __restrict__ bc1,
                           const float* __restrict__ Wc2, const float* __restrict__ bc2,
                           float* __restrict__ out) {
    int g = threadIdx.x;
    if (g >= NG) return;
    float invc = 1.f / fmaxf(cnt[g], 1.f);
    float pooled[CC];
    #pragma unroll 8
    for (int c = 0; c < CC; c++) pooled[c] = psum[g * CC + c] * invc;
    float r = bc2[0];
    for (int j = 0; j < 64; j++) {
        float z = bc1[j];
        #pragma unroll 8
        for (int c = 0; c < CC; c++) z += pooled[c] * Wc1[c * 64 + j];
        r += fmaxf(z, 0.f) * Wc2[j];
    }
    out[g] = r;
}

// ---------------- launch ----------------
extern "C" void kernel_launch(void* const* d_in, const int* in_sizes, int n_in,
                              void* d_out, int out_size) {
    const int N = NN, E = EE;
    const int*   x     = (const int*)d_in[0];
    const int*   ei    = (const int*)d_in[1];
    const int*   src   = ei;
    const int*   dst   = ei + E;
    const int*   batch = (const int*)d_in[2];
    const float* emb   = (const float*)d_in[3];

    const float *Wq0 = (const float*)d_in[4],  *bq0 = (const float*)d_in[5];
    const float *Wk0 = (const float*)d_in[6],  *bk0 = (const float*)d_in[7];
    const float *Wv0 = (const float*)d_in[8],  *bv0 = (const float*)d_in[9];
    const float *Ws0 = (const float*)d_in[10], *bs0 = (const float*)d_in[11];
    const float *Wb0 = (const float*)d_in[12];
    const float *g0  = (const float*)d_in[13], *be0 = (const float*)d_in[14];
    const float *Wq1 = (const float*)d_in[15], *bq1 = (const float*)d_in[16];
    const float *Wk1 = (const float*)d_in[17], *bk1 = (const float*)d_in[18];
    const float *Wv1 = (const float*)d_in[19], *bv1 = (const float*)d_in[20];
    const float *Ws1 = (const float*)d_in[21], *bs1 = (const float*)d_in[22];
    const float *Wb1 = (const float*)d_in[23];
    const float *g1  = (const float*)d_in[24], *be1 = (const float*)d_in[25];
    const float *Wc1 = (const float*)d_in[26], *bc1 = (const float*)d_in[27];
    const float *Wc2 = (const float*)d_in[28], *bc2 = (const float*)d_in[29];

    __nv_bfloat16 *hb, *qbb, *kv, *h1, *h2, *Wt;
    float *skip, *bcat, *pool, *cnt;
    int *deg, *rowptr, *wofs, *col, *bsum, *bsum2;
    cudaGetSymbolAddress((void**)&hb,     g_hb);
    cudaGetSymbolAddress((void**)&qbb,    g_qb);
    cudaGetSymbolAddress((void**)&kv,     g_kv);
    cudaGetSymbolAddress((void**)&skip,   g_skip);
    cudaGetSymbolAddress((void**)&h1,     g_h1);
    cudaGetSymbolAddress((void**)&h2,     g_h2);
    cudaGetSymbolAddress((void**)&Wt,     g_Wt);
    cudaGetSymbolAddress((void**)&bcat,   g_bcat);
    cudaGetSymbolAddress((void**)&pool,   g_pool);
    cudaGetSymbolAddress((void**)&cnt,    g_cnt);
    cudaGetSymbolAddress((void**)&deg,    g_deg);
    cudaGetSymbolAddress((void**)&rowptr, g_rowptr);
    cudaGetSymbolAddress((void**)&wofs,   g_wofs);
    cudaGetSymbolAddress((void**)&col,    g_col);
    cudaGetSymbolAddress((void**)&bsum,   g_bsum);
    cudaGetSymbolAddress((void**)&bsum2,  g_bsum2);

    cudaFuncSetAttribute(gemm_bf16_kernel<8>, cudaFuncAttributeMaxDynamicSharedMemorySize,
                         GEMM_SMEM);
    cudaFuncSetAttribute(gemm_bf16_kernel<4>, cudaFuncAttributeMaxDynamicSharedMemorySize,
                         GEMM_SMEM);

    const int NB = (N + 255) / 256;
    dim3 ggrid(NOUT / GBN, (N + GBM - 1) / GBM);   // (26, 391)
    dim3 pgrid(NOUT / 32, 256 / 32);
    dim3 pgrid1(NOUT / 32, 128 / 32);
    dim3 pthr(32, 8);

    // launches ordered so gemm #0 is my 5th launch (profiled slot)
    cudaMemsetAsync(deg, 0, N * sizeof(int));                                   // 1
    hist_kernel<<<(E + 255) / 256, 256>>>(dst, deg, E);                         // 2
    embed_kernel<<<(N * 32 + 255) / 256, 256>>>(x, emb, hb, N);                 // 3
    pack_kernel<<<pgrid, pthr>>>(Wq0, Wk0, Wv0, Ws0, bq0, bk0, bv0, bs0,
                                 Wt, bcat, 256);                                // 4
    gemm_bf16_kernel<8><<<ggrid, 256, GEMM_SMEM>>>(hb, Wt, bcat, qbb, kv, skip,
                                                   N, 256);                     // 5 <- profiled
    scan_block_kernel<<<NB, 256>>>(deg, rowptr, bsum, N);                       // 6
    scan_bsum_kernel<<<1, 256>>>(bsum, bsum2, NB);                              // 7
    scan_add_kernel<<<NB, 256>>>(rowptr, bsum2, wofs, N);                       // 8
    scatter_kernel<<<(E + 255) / 256, 256>>>(src, dst, wofs, col, E);           // 9
    attn_fused_kernel<<<N, 256>>>(qbb, kv, rowptr, col, skip, Wb0, g0, be0,
                                  (const __nv_bfloat16*)nullptr, h1);           // 10

    pack_kernel<<<pgrid1, pthr>>>(Wq1, Wk1, Wv1, Ws1, bq1, bk1, bv1, bs1,
                                  Wt, bcat, 128);                               // 11
    gemm_bf16_kernel<4><<<ggrid, 256, GEMM_SMEM>>>(h1, Wt, bcat, qbb, kv, skip,
                                                   N, 128);                     // 12
    attn_fused_kernel<<<N, 256>>>(qbb, kv, rowptr, col, skip, Wb1, g1, be1,
                                  h1, h2);                                      // 13

    cudaMemsetAsync(pool, 0, NG * CC * sizeof(float));
    cudaMemsetAsync(cnt, 0, NG * sizeof(float));
    pool_kernel<<<(N + 63) / 64, 128>>>(h2, batch, pool, cnt, N);
    cls_kernel<<<1, 64>>>(pool, cnt, Wc1, bc1, Wc2, bc2, (float*)d_out);
}

// round 15
// speedup vs baseline: 1.2078x; 1.0561x over previous
#include <cuda_runtime.h>
#include <cuda_bf16.h>
#include <math.h>
#include <stdint.h>

// ---------------- problem constants ----------------
#define NN 50000
#define EE 400000
#define HH 8
#define CC 128
#define EMB 256
#define NG 64
#define NOUT 3328
#define NREAL 3200
#define OFF_K 1024
#define OFF_V 2048
#define OFF_S 3072
#define KV_W 2048
#define QB_W 1024

// ---------------- scratch ----------------
__device__ __nv_bfloat16 g_hb[(size_t)NN * EMB];
__device__ __nv_bfloat16 g_qb[(size_t)NN * QB_W];
__device__ __nv_bfloat16 g_kv[(size_t)NN * KV_W];
__device__ float g_skip[(size_t)NN * CC];
__device__ __nv_bfloat16 g_h1[(size_t)NN * CC];
__device__ __nv_bfloat16 g_h2[(size_t)NN * CC];
__device__ __nv_bfloat16 g_Wt[(size_t)NOUT * EMB];
__device__ float g_bcat[NOUT];
__device__ float g_pool[NG * CC];
__device__ float g_cnt[NG];
__device__ int   g_deg[NN];
__device__ int   g_rowptr[NN + 1];
__device__ int   g_wofs[NN + 1];
__device__ int   g_col[EE];
__device__ int   g_bsum[256];
__device__ int   g_bsum2[256];

// ---------------- CSR build ----------------
__global__ void hist_kernel(const int* __restrict__ dst, int* __restrict__ deg, int E) {
    int e = blockIdx.x * blockDim.x + threadIdx.x;
    if (e < E) atomicAdd(&deg[dst[e]], 1);
}

__global__ void scan_block_kernel(const int* __restrict__ deg, int* __restrict__ rowptr,
                                  int* __restrict__ bsum, int n) {
    __shared__ int s[256];
    int i = blockIdx.x * 256 + threadIdx.x;
    int v = (i < n) ? deg[i] : 0;
    s[threadIdx.x] = v;
    __syncthreads();
    #pragma unroll
    for (int off = 1; off < 256; off <<= 1) {
        int t = (threadIdx.x >= off) ? s[threadIdx.x - off] : 0;
        __syncthreads();
        s[threadIdx.x] += t;
        __syncthreads();
    }
    if (i < n) rowptr[i + 1] = s[threadIdx.x];
    if (threadIdx.x == 255) bsum[blockIdx.x] = s[255];
}

__global__ void scan_bsum_kernel(const int* __restrict__ bsum, int* __restrict__ bsum2, int nb) {
    __shared__ int s[256];
    int t = threadIdx.x;
    int v = (t < nb) ? bsum[t] : 0;
    s[t] = v;
    __syncthreads();
    #pragma unroll
    for (int off = 1; off < 256; off <<= 1) {
        int x = (t >= off) ? s[t - off] : 0;
        __syncthreads();
        s[t] += x;
        __syncthreads();
    }
    if (t < nb) bsum2[t] = s[t] - v;   // exclusive
}

__global__ void scan_add_kernel(int* __restrict__ rowptr, const int* __restrict__ bsum2,
                                int* __restrict__ wofs, int n) {
    int i = blockIdx.x * 256 + threadIdx.x;
    if (i < n) {
        int v = rowptr[i + 1] + bsum2[blockIdx.x];
        rowptr[i + 1] = v;
        wofs[i + 1] = v;
    }
    if (i == 0) { rowptr[0] = 0; wofs[0] = 0; }
}

__global__ void scatter_kernel(const int* __restrict__ src, const int* __restrict__ dst,
                               int* __restrict__ wofs, int* __restrict__ col, int E) {
    int e = blockIdx.x * blockDim.x + threadIdx.x;
    if (e < E) {
        int p = atomicAdd(&wofs[dst[e]], 1);
        col[p] = src[e];
    }
}

// ---------------- embedding gather ----------------
__global__ void embed_kernel(const int* __restrict__ x, const float* __restrict__ emb,
                             __nv_bfloat16* __restrict__ hb, int N) {
    int idx = blockIdx.x * blockDim.x + threadIdx.x;
    if (idx >= N * 32) return;
    int n  = idx >> 5;
    int g8 = (idx & 31) << 3;
    const float* p = emb + (size_t)x[n] * EMB + g8;
    float4 a = *(const float4*)p;
    float4 b = *(const float4*)(p + 4);
    __nv_bfloat162 o[4];
    o[0] = __float22bfloat162_rn(make_float2(a.x, a.y));
    o[1] = __float22bfloat162_rn(make_float2(a.z, a.w));
    o[2] = __float22bfloat162_rn(make_float2(b.x, b.y));
    o[3] = __float22bfloat162_rn(make_float2(b.z, b.w));
    *(uint4*)(hb + (size_t)n * EMB + g8) = *(uint4*)o;
}

// ---------------- weight pack: tiled transpose ----------------
__global__ void pack_kernel(const float* __restrict__ Wq, const float* __restrict__ Wk,
                            const float* __restrict__ Wv, const float* __restrict__ Ws,
                            const float* __restrict__ bq, const float* __restrict__ bk,
                            const float* __restrict__ bv, const float* __restrict__ bs,
                            __nv_bfloat16* __restrict__ Wt, float* __restrict__ bcat, int K) {
    __shared__ float t[32][33];
    int n0 = blockIdx.x * 32, k0 = blockIdx.y * 32;
    int tx = threadIdx.x, ty = threadIdx.y;
    #pragma unroll
    for (int i = 0; i < 4; i++) {
        int k = k0 + ty + i * 8;
        int n = n0 + tx;
        float v;
        if (n < 1024)       v = Wq[k * 1024 + n];
        else if (n < 2048)  v = Wk[k * 1024 + (n - 1024)];
        else if (n < 3072)  v = Wv[k * 1024 + (n - 2048)];
        else if (n < NREAL) v = Ws[k * 128  + (n - 3072)];
        else                v = 0.f;
        t[ty + i * 8][tx] = v;
    }
    if (k0 == 0 && ty == 0) {
        int n = n0 + tx;
        float b;
        if (n < 1024)       b = bq[n];
        else if (n < 2048)  b = bk[n - 1024];
        else if (n < 3072)  b = bv[n - 2048];
        else if (n < NREAL) b = bs[n - 3072];
        else                b = 0.f;
        bcat[n] = b;
    }
    __syncthreads();
    #pragma unroll
    for (int i = 0; i < 4; i++) {
        int n = n0 + ty + i * 8;
        int k = k0 + tx;
        Wt[(size_t)n * K + k] = __float2bfloat16(t[tx][ty + i * 8]);
    }
}

// ---------------- bf16 GEMM: 128x128x32, 3-stage ring, ldmatrix, 512 thr (32x32 warp) ----------------
__device__ __forceinline__ void mma_bf16(float* c, const uint32_t* a, const uint32_t* b) {
    asm volatile(
        "mma.sync.aligned.m16n8k16.row.col.f32.bf16.bf16.f32 "
        "{%0,%1,%2,%3}, {%4,%5,%6,%7}, {%8,%9}, {%0,%1,%2,%3};"
        : "+f"(c[0]), "+f"(c[1]), "+f"(c[2]), "+f"(c[3])
        : "r"(a[0]), "r"(a[1]), "r"(a[2]), "r"(a[3]), "r"(b[0]), "r"(b[1]));
}

__device__ __forceinline__ void cp16(uint32_t dst, const void* src) {
    asm volatile("cp.async.cg.shared.global [%0], [%1], 16;" :: "r"(dst), "l"(src));
}

__device__ __forceinline__ void ldsm4(uint32_t& r0, uint32_t& r1, uint32_t& r2, uint32_t& r3,
                                      uint32_t addr) {
    asm volatile("ldmatrix.sync.aligned.m8n8.x4.shared.b16 {%0,%1,%2,%3}, [%4];"
        : "=r"(r0), "=r"(r1), "=r"(r2), "=r"(r3) : "r"(addr));
}

#define GBM 128
#define GBN 128
#define GBK 32
#define RS2 20
#define STG (128 * RS2)
#define STG4 (STG * 4)
#define GEMM_SMEM (6 * STG4)        // 61440 bytes

__device__ __forceinline__ void epi_store(__nv_bfloat16* __restrict__ qb,
                                          __nv_bfloat16* __restrict__ kv,
                                          float* __restrict__ skip,
                                          int r, int c, float2 o) {
    if (c < OFF_K) {
        *(__nv_bfloat162*)(qb + (size_t)r * QB_W + c) = __float22bfloat162_rn(o);
    } else if (c < OFF_S) {
        bool isk = c < OFF_V;
        int ch = isk ? (c - OFF_K) : (c - OFF_V);
        int head = ch >> 7, within = ch & 127;
        int slot = head * 256 + (within >> 2) * 8 + (within & 3) + (isk ? 0 : 4);
        *(__nv_bfloat162*)(kv + (size_t)r * KV_W + slot) = __float22bfloat162_rn(o);
    } else if (c < NREAL) {
        *(float2*)(skip + (size_t)r * CC + (c - OFF_S)) = o;
    }
}

template<int NITER>
__global__ __launch_bounds__(512, 2)
void gemm_bf16_kernel(const __nv_bfloat16* __restrict__ A, const __nv_bfloat16* __restrict__ Bt,
                      const float* __restrict__ bias,
                      __nv_bfloat16* __restrict__ qb, __nv_bfloat16* __restrict__ kv,
                      float* __restrict__ skip, int M, int K) {
    extern __shared__ uint32_t smem[];
    uint32_t sbase = (uint32_t)__cvta_generic_to_shared(smem);

    int bm = blockIdx.y * GBM;
    int bn = blockIdx.x * GBN;
    int tid = threadIdx.x;
    int wid = tid >> 5, lane = tid & 31;
    int wm = (wid >> 2) * 32;           // 4 warp-rows of 32
    int wn = (wid & 3) * 32;            // 4 warp-cols of 32
    int gid = lane >> 2, tig = lane & 3;

    float acc[2][4][4];
    #pragma unroll
    for (int i = 0; i < 2; i++)
        #pragma unroll
        for (int j = 0; j < 4; j++)
            #pragma unroll
            for (int q = 0; q < 4; q++) acc[i][j][q] = 0.f;

    // cp.async loaders: 4 threads per row, one cp16 per matrix per thread
    int lr = tid >> 2, lp = tid & 3;
    int rsafe = min(bm + lr, M - 1);
    const __nv_bfloat16* aPtr = A + (size_t)rsafe * K + lp * 8;
    const __nv_bfloat16* bPtr = Bt + (size_t)(bn + lr) * K + lp * 8;
    uint32_t aD = sbase + (lr * RS2 + lp * 4) * 4;
    uint32_t bD = sbase + 3 * STG4 + (lr * RS2 + lp * 4) * 4;

    // ldmatrix per-lane row/col mapping
    int l8 = lane & 7;
    int rowA = l8 + ((lane >> 3) & 1) * 8;
    int colA = (lane >> 4) * 4;
    int rowB = l8 + (lane >> 4) * 8;
    int colB = ((lane >> 3) & 1) * 4;

    // prologue: stages 0 and 1
    cp16(aD, aPtr);
    cp16(bD, bPtr);
    asm volatile("cp.async.commit_group;");
    if (NITER > 1) {
        cp16(aD + STG4, aPtr + 32);
        cp16(bD + STG4, bPtr + 32);
    }
    asm volatile("cp.async.commit_group;");

    #pragma unroll
    for (int it = 0; it < NITER; it++) {
        asm volatile("cp.async.wait_group 1;");
        __syncthreads();
        if (it + 2 < NITER) {
            int s = (it + 2) % 3;
            int kEl = (it + 2) * GBK;
            cp16(aD + s * STG4, aPtr + kEl);
            cp16(bD + s * STG4, bPtr + kEl);
        }
        asm volatile("cp.async.commit_group;");

        uint32_t sA = sbase + (it % 3) * STG4;
        uint32_t sB = sbase + 3 * STG4 + (it % 3) * STG4;
        #pragma unroll
        for (int kk2 = 0; kk2 < 16; kk2 += 8) {
            uint32_t af[2][4], bf[4][2];
            #pragma unroll
            for (int i = 0; i < 2; i++)
                ldsm4(af[i][0], af[i][1], af[i][2], af[i][3],
                      sA + ((wm + i * 16 + rowA) * RS2 + colA + kk2) * 4);
            #pragma unroll
            for (int j = 0; j < 4; j += 2)
                ldsm4(bf[j][0], bf[j][1], bf[j + 1][0], bf[j + 1][1],
                      sB + ((wn + j * 8 + rowB) * RS2 + colB + kk2) * 4);
            #pragma unroll
            for (int i = 0; i < 2; i++)
                #pragma unroll
                for (int j = 0; j < 4; j++)
                    mma_bf16(acc[i][j], af[i], bf[j]);
        }
    }

    #pragma unroll
    for (int i = 0; i < 2; i++) {
        int r0 = bm + wm + i * 16 + gid;
        #pragma unroll
        for (int j = 0; j < 4; j++) {
            int c = bn + wn + j * 8 + tig * 2;
            float2 bb = *(const float2*)(bias + c);
            if (r0 < M)
                epi_store(qb, kv, skip, r0, c,
                          make_float2(acc[i][j][0] + bb.x, acc[i][j][1] + bb.y));
            if (r0 + 8 < M)
                epi_store(qb, kv, skip, r0 + 8, c,
                          make_float2(acc[i][j][2] + bb.x, acc[i][j][3] + bb.y));
        }
    }
}

// ---------------- fused attention + beta-gate + LayerNorm + ReLU (ILP x2, R9 exact) ----------------
__global__ __launch_bounds__(256)
void attn_fused_kernel(const __nv_bfloat16* __restrict__ qb, const __nv_bfloat16* __restrict__ kv,
                       const int* __restrict__ rowptr, const int* __restrict__ col,
                       const float* __restrict__ skip, const float* __restrict__ Wb,
                       const float* __restrict__ gam, const float* __restrict__ bet,
                       const __nv_bfloat16* __restrict__ res, __nv_bfloat16* __restrict__ out) {
    __shared__ float sm[HH * CC + CC];
    int node = blockIdx.x;
    int wid  = threadIdx.x >> 5;
    int lane = threadIdx.x & 31;
    const float scale = 0.0883883476483184f; // 1/sqrt(128)

    uint2 qr = *(const uint2*)(qb + (size_t)node * QB_W + wid * CC + lane * 4);
    float2 qa = __bfloat1622float2(*(const __nv_bfloat162*)&qr.x);
    float2 qc = __bfloat1622float2(*(const __nv_bfloat162*)&qr.y);
    int e0 = rowptr[node], e1 = rowptr[node + 1];
    size_t off = (size_t)wid * 256 + lane * 8;

    float m0 = -1e30f, den0 = 0.f, m1 = -1e30f, den1 = 0.f;
    float4 a0 = make_float4(0.f, 0.f, 0.f, 0.f);
    float4 a1 = make_float4(0.f, 0.f, 0.f, 0.f);

    int e = e0;
    for (; e + 1 < e1; e += 2) {
        int s0 = col[e], s1 = col[e + 1];
        uint4 p0 = *(const uint4*)(kv + (size_t)s0 * KV_W + off);
        uint4 p1 = *(const uint4*)(kv + (size_t)s1 * KV_W + off);
        float2 k0a = __bfloat1622float2(*(const __nv_bfloat162*)&p0.x);
        float2 k0b = __bfloat1622float2(*(const __nv_bfloat162*)&p0.y);
        float2 k1a = __bfloat1622float2(*(const __nv_bfloat162*)&p1.x);
        float2 k1b = __bfloat1622float2(*(const __nv_bfloat162*)&p1.y);
        float d0 = qa.x * k0a.x + qa.y * k0a.y + qc.x * k0b.x + qc.y * k0b.y;
        float d1 = qa.x * k1a.x + qa.y * k1a.y + qc.x * k1b.x + qc.y * k1b.y;
        #pragma unroll
        for (int o = 16; o; o >>= 1) {
            d0 += __shfl_xor_sync(0xffffffffu, d0, o);
            d1 += __shfl_xor_sync(0xffffffffu, d1, o);
        }
        float2 v0a = __bfloat1622float2(*(const __nv_bfloat162*)&p0.z);
        float2 v0b = __bfloat1622float2(*(const __nv_bfloat162*)&p0.w);
        float2 v1a = __bfloat1622float2(*(const __nv_bfloat162*)&p1.z);
        float2 v1b = __bfloat1622float2(*(const __nv_bfloat162*)&p1.w);
        {
            float lg = d0 * scale;
            float mn = fmaxf(m0, lg);
            float cr = __expf(m0 - mn), p = __expf(lg - mn);
            den0 = den0 * cr + p;
            a0.x = a0.x * cr + p * v0a.x; a0.y = a0.y * cr + p * v0a.y;
            a0.z = a0.z * cr + p * v0b.x; a0.w = a0.w * cr + p * v0b.y;
            m0 = mn;
        }
        {
            float lg = d1 * scale;
            float mn = fmaxf(m1, lg);
            float cr = __expf(m1 - mn), p = __expf(lg - mn);
            den1 = den1 * cr + p;
            a1.x = a1.x * cr + p * v1a.x; a1.y = a1.y * cr + p * v1a.y;
            a1.z = a1.z * cr + p * v1b.x; a1.w = a1.w * cr + p * v1b.y;
            m1 = mn;
        }
    }
    if (e < e1) {
        int s0 = col[e];
        uint4 p0 = *(const uint4*)(kv + (size_t)s0 * KV_W + off);
        float2 k0a = __bfloat1622float2(*(const __nv_bfloat162*)&p0.x);
        float2 k0b = __bfloat1622float2(*(const __nv_bfloat162*)&p0.y);
        float d0 = qa.x * k0a.x + qa.y * k0a.y + qc.x * k0b.x + qc.y * k0b.y;
        #pragma unroll
        for (int o = 16; o; o >>= 1) d0 += __shfl_xor_sync(0xffffffffu, d0, o);
        float2 v0a = __bfloat1622float2(*(const __nv_bfloat162*)&p0.z);
        float2 v0b = __bfloat1622float2(*(const __nv_bfloat162*)&p0.w);
        float lg = d0 * scale;
        float mn = fmaxf(m0, lg);
        float cr = __expf(m0 - mn), p = __expf(lg - mn);
        den0 = den0 * cr + p;
        a0.x = a0.x * cr + p * v0a.x; a0.y = a0.y * cr + p * v0a.y;
        a0.z = a0.z * cr + p * v0b.x; a0.w = a0.w * cr + p * v0b.y;
        m0 = mn;
    }
    float M = fmaxf(m0, m1);
    float c0 = __expf(m0 - M), c1 = __expf(m1 - M);
    float den = den0 * c0 + den1 * c1;
    float4 acc;
    acc.x = a0.x * c0 + a1.x * c1;
    acc.y = a0.y * c0 + a1.y * c1;
    acc.z = a0.z * c0 + a1.z * c1;
    acc.w = a0.w * c0 + a1.w * c1;

    float inv = 1.f / (den + 1e-16f);
    sm[wid * CC + lane * 4 + 0] = acc.x * inv;
    sm[wid * CC + lane * 4 + 1] = acc.y * inv;
    sm[wid * CC + lane * 4 + 2] = acc.z * inv;
    sm[wid * CC + lane * 4 + 3] = acc.w * inv;
    __syncthreads();

    if (threadIdx.x < CC) {
        float s = 0.f;
        #pragma unroll
        for (int h = 0; h < HH; h++) s += sm[h * CC + threadIdx.x];
        sm[HH * CC + threadIdx.x] = s * 0.125f;
    }
    __syncthreads();

    if (threadIdx.x < 32) {
        int c = threadIdx.x * 4;
        float4 a  = *(float4*)&sm[HH * CC + c];
        float4 xr = *(const float4*)(skip + (size_t)node * CC + c);
        float4 w0 = *(const float4*)(Wb + c);
        float4 w1 = *(const float4*)(Wb + 128 + c);
        float4 w2 = *(const float4*)(Wb + 256 + c);

        float t = a.x * w0.x + a.y * w0.y + a.z * w0.z + a.w * w0.w
                + xr.x * w1.x + xr.y * w1.y + xr.z * w1.z + xr.w * w1.w
                + (a.x - xr.x) * w2.x + (a.y - xr.y) * w2.y
                + (a.z - xr.z) * w2.z + (a.w - xr.w) * w2.w;
        #pragma unroll
        for (int o = 16; o; o >>= 1) t += __shfl_xor_sync(0xffffffffu, t, o);
        float beta = 1.f / (1.f + __expf(-t));

        float4 y;
        y.x = beta * xr.x + (1.f - beta) * a.x;
        y.y = beta * xr.y + (1.f - beta) * a.y;
        y.z = beta * xr.z + (1.f - beta) * a.z;
        y.w = beta * xr.w + (1.f - beta) * a.w;
        if (res) {
            uint2 rr = *(const uint2*)(res + (size_t)node * CC + c);
            float2 r0 = __bfloat1622float2(*(const __nv_bfloat162*)&rr.x);
            float2 r1 = __bfloat1622float2(*(const __nv_bfloat162*)&rr.y);
            y.x += r0.x; y.y += r0.y; y.z += r1.x; y.w += r1.y;
        }
        float s = y.x + y.y + y.z + y.w;
        #pragma unroll
        for (int o = 16; o; o >>= 1) s += __shfl_xor_sync(0xffffffffu, s, o);
        float mu = s * (1.f / 128.f);
        float dx0 = y.x - mu, dx1 = y.y - mu, dx2 = y.z - mu, dx3 = y.w - mu;
        float q = dx0 * dx0 + dx1 * dx1 + dx2 * dx2 + dx3 * dx3;
        #pragma unroll
        for (int o = 16; o; o >>= 1) q += __shfl_xor_sync(0xffffffffu, q, o);
        float rstd = rsqrtf(q * (1.f / 128.f) + 1e-5f);
        float4 gg = *(const float4*)(gam + c);
        float4 bb = *(const float4*)(bet + c);
        float2 o0, o1;
        o0.x = fmaxf(dx0 * rstd * gg.x + bb.x, 0.f);
        o0.y = fmaxf(dx1 * rstd * gg.y + bb.y, 0.f);
        o1.x = fmaxf(dx2 * rstd * gg.z + bb.z, 0.f);
        o1.y = fmaxf(dx3 * rstd * gg.w + bb.w, 0.f);
        uint2 ow;
        *(__nv_bfloat162*)&ow.x = __float22bfloat162_rn(o0);
        *(__nv_bfloat162*)&ow.y = __float22bfloat162_rn(o1);
        *(uint2*)(out + (size_t)node * CC + c) = ow;
    }
}

// ---------------- pooling (batch sorted) ----------------
__global__ __launch_bounds__(128)
void pool_kernel(const __nv_bfloat16* __restrict__ h, const int* __restrict__ batch,
                 float* __restrict__ psum, float* __restrict__ cnt, int N) {
    int c = threadIdx.x;
    int n0 = blockIdx.x * 64;
    int n1 = min(n0 + 64, N);
    int cur = batch[n0];
    float s = 0.f;
    float k = 0.f;
    for (int n = n0; n < n1; n++) {
        int b = batch[n];
        if (b != cur) {
            atomicAdd(&psum[cur * CC + c], s);
            if (c == 0) atomicAdd(&cnt[cur], k);
            s = 0.f; k = 0.f; cur = b;
        }
        s += __bfloat162float(h[(size_t)n * CC + c]);
        k += 1.f;
    }
    atomicAdd(&psum[cur * CC + c], s);
    if (c == 0) atomicAdd(&cnt[cur], k);
}

// ---------------- classifier ----------------
__global__ void cls_kernel(const float* __restrict__ psum, const float* __restrict__ cnt,
                           const float* __restrict__ Wc1, const float* __restrict__ bc1,
                           const float* __restrict__ Wc2, const float* __restrict__ bc2,
                           float* __restrict__ out) {
    int g = threadIdx.x;
    if (g >= NG) return;
    float invc = 1.f / fmaxf(cnt[g], 1.f);
    float pooled[CC];
    #pragma unroll 8
    for (int c = 0; c < CC; c++) pooled[c] = psum[g * CC + c] * invc;
    float r = bc2[0];
    for (int j = 0; j < 64; j++) {
        float z = bc1[j];
        #pragma unroll 8
        for (int c = 0; c < CC; c++) z += pooled[c] * Wc1[c * 64 + j];
        r += fmaxf(z, 0.f) * Wc2[j];
    }
    out[g] = r;
}

// ---------------- launch ----------------
extern "C" void kernel_launch(void* const* d_in, const int* in_sizes, int n_in,
                              void* d_out, int out_size) {
    const int N = NN, E = EE;
    const int*   x     = (const int*)d_in[0];
    const int*   ei    = (const int*)d_in[1];
    const int*   src   = ei;
    const int*   dst   = ei + E;
    const int*   batch = (const int*)d_in[2];
    const float* emb   = (const float*)d_in[3];

    const float *Wq0 = (const float*)d_in[4],  *bq0 = (const float*)d_in[5];
    const float *Wk0 = (const float*)d_in[6],  *bk0 = (const float*)d_in[7];
    const float *Wv0 = (const float*)d_in[8],  *bv0 = (const float*)d_in[9];
    const float *Ws0 = (const float*)d_in[10], *bs0 = (const float*)d_in[11];
    const float *Wb0 = (const float*)d_in[12];
    const float *g0  = (const float*)d_in[13], *be0 = (const float*)d_in[14];
    const float *Wq1 = (const float*)d_in[15], *bq1 = (const float*)d_in[16];
    const float *Wk1 = (const float*)d_in[17], *bk1 = (const float*)d_in[18];
    const float *Wv1 = (const float*)d_in[19], *bv1 = (const float*)d_in[20];
    const float *Ws1 = (const float*)d_in[21], *bs1 = (const float*)d_in[22];
    const float *Wb1 = (const float*)d_in[23];
    const float *g1  = (const float*)d_in[24], *be1 = (const float*)d_in[25];
    const float *Wc1 = (const float*)d_in[26], *bc1 = (const float*)d_in[27];
    const float *Wc2 = (const float*)d_in[28], *bc2 = (const float*)d_in[29];

    __nv_bfloat16 *hb, *qbb, *kv, *h1, *h2, *Wt;
    float *skip, *bcat, *pool, *cnt;
    int *deg, *rowptr, *wofs, *col, *bsum, *bsum2;
    cudaGetSymbolAddress((void**)&hb,     g_hb);
    cudaGetSymbolAddress((void**)&qbb,    g_qb);
    cudaGetSymbolAddress((void**)&kv,     g_kv);
    cudaGetSymbolAddress((void**)&skip,   g_skip);
    cudaGetSymbolAddress((void**)&h1,     g_h1);
    cudaGetSymbolAddress((void**)&h2,     g_h2);
    cudaGetSymbolAddress((void**)&Wt,     g_Wt);
    cudaGetSymbolAddress((void**)&bcat,   g_bcat);
    cudaGetSymbolAddress((void**)&pool,   g_pool);
    cudaGetSymbolAddress((void**)&cnt,    g_cnt);
    cudaGetSymbolAddress((void**)&deg,    g_deg);
    cudaGetSymbolAddress((void**)&rowptr, g_rowptr);
    cudaGetSymbolAddress((void**)&wofs,   g_wofs);
    cudaGetSymbolAddress((void**)&col,    g_col);
    cudaGetSymbolAddress((void**)&bsum,   g_bsum);
    cudaGetSymbolAddress((void**)&bsum2,  g_bsum2);

    cudaFuncSetAttribute(gemm_bf16_kernel<8>, cudaFuncAttributeMaxDynamicSharedMemorySize,
                         GEMM_SMEM);
    cudaFuncSetAttribute(gemm_bf16_kernel<4>, cudaFuncAttributeMaxDynamicSharedMemorySize,
                         GEMM_SMEM);

    const int NB = (N + 255) / 256;
    dim3 ggrid(NOUT / GBN, (N + GBM - 1) / GBM);   // (26, 391)
    dim3 pgrid(NOUT / 32, 256 / 32);
    dim3 pgrid1(NOUT / 32, 128 / 32);
    dim3 pthr(32, 8);

    // launches ordered so gemm #0 is my 5th launch (profiled slot)
    cudaMemsetAsync(deg, 0, N * sizeof(int));                                   // 1
    hist_kernel<<<(E + 255) / 256, 256>>>(dst, deg, E);                         // 2
    embed_kernel<<<(N * 32 + 255) / 256, 256>>>(x, emb, hb, N);                 // 3
    pack_kernel<<<pgrid, pthr>>>(Wq0, Wk0, Wv0, Ws0, bq0, bk0, bv0, bs0,
                                 Wt, bcat, 256);                                // 4
    gemm_bf16_kernel<8><<<ggrid, 512, GEMM_SMEM>>>(hb, Wt, bcat, qbb, kv, skip,
                                                   N, 256);                     // 5 <- profiled
    scan_block_kernel<<<NB, 256>>>(deg, rowptr, bsum, N);                       // 6
    scan_bsum_kernel<<<1, 256>>>(bsum, bsum2, NB);                              // 7
    scan_add_kernel<<<NB, 256>>>(rowptr, bsum2, wofs, N);                       // 8
    scatter_kernel<<<(E + 255) / 256, 256>>>(src, dst, wofs, col, E);           // 9
    attn_fused_kernel<<<N, 256>>>(qbb, kv, rowptr, col, skip, Wb0, g0, be0,
                                  (const __nv_bfloat16*)nullptr, h1);           // 10

    pack_kernel<<<pgrid1, pthr>>>(Wq1, Wk1, Wv1, Ws1, bq1, bk1, bv1, bs1,
                                  Wt, bcat, 128);                               // 11
    gemm_bf16_kernel<4><<<ggrid, 512, GEMM_SMEM>>>(h1, Wt, bcat, qbb, kv, skip,
                                                   N, 128);                     // 12
    attn_fused_kernel<<<N, 256>>>(qbb, kv, rowptr, col, skip, Wb1, g1, be1,
                                  h1, h2);                                      // 13

    cudaMemsetAsync(pool, 0, NG * CC * sizeof(float));
    cudaMemsetAsync(cnt, 0, NG * sizeof(float));
    pool_kernel<<<(N + 63) / 64, 128>>>(h2, batch, pool, cnt, N);
    cls_kernel<<<1, 64>>>(pool, cnt, Wc1, bc1, Wc2, bc2, (float*)d_out);
}

// round 16
// speedup vs baseline: 1.2185x; 1.0089x over previous
#include <cuda_runtime.h>
#include <cuda_bf16.h>
#include <math.h>
#include <stdint.h>

// ---------------- problem constants ----------------
#define NN 50000
#define EE 400000
#define HH 8
#define CC 128
#define EMB 256
#define NG 64
#define NOUT 3328
#define NREAL 3200
#define OFF_K 1024
#define OFF_V 2048
#define OFF_S 3072
#define KV_W 2048
#define QB_W 1024

// ---------------- scratch ----------------
__device__ __nv_bfloat16 g_hb[(size_t)NN * EMB];
__device__ __nv_bfloat16 g_qb[(size_t)NN * QB_W];
__device__ __nv_bfloat16 g_kv[(size_t)NN * KV_W];
__device__ float g_skip[(size_t)NN * CC];
__device__ __nv_bfloat16 g_h1[(size_t)NN * CC];
__device__ __nv_bfloat16 g_h2[(size_t)NN * CC];
__device__ __nv_bfloat16 g_Wt[(size_t)NOUT * EMB];   // layer0 weights (K=256)
__device__ __nv_bfloat16 g_Wt1[(size_t)NOUT * 128];  // layer1 weights (K=128)
__device__ float g_bcat[NOUT];
__device__ float g_bcat1[NOUT];
__device__ float g_pool[NG * CC];
__device__ float g_cnt[NG];
__device__ int   g_deg[NN];
__device__ int   g_rowptr[NN + 1];
__device__ int   g_wofs[NN + 1];
__device__ int   g_col[EE];
__device__ int   g_bsum[256];
__device__ int   g_bsum2[256];

// ---------------- CSR build ----------------
__global__ void hist_kernel(const int* __restrict__ dst, int* __restrict__ deg, int E) {
    int e = blockIdx.x * blockDim.x + threadIdx.x;
    if (e < E) atomicAdd(&deg[dst[e]], 1);
}

__global__ void scan_block_kernel(const int* __restrict__ deg, int* __restrict__ rowptr,
                                  int* __restrict__ bsum, int n) {
    __shared__ int s[256];
    int i = blockIdx.x * 256 + threadIdx.x;
    int v = (i < n) ? deg[i] : 0;
    s[threadIdx.x] = v;
    __syncthreads();
    #pragma unroll
    for (int off = 1; off < 256; off <<= 1) {
        int t = (threadIdx.x >= off) ? s[threadIdx.x - off] : 0;
        __syncthreads();
        s[threadIdx.x] += t;
        __syncthreads();
    }
    if (i < n) rowptr[i + 1] = s[threadIdx.x];
    if (threadIdx.x == 255) bsum[blockIdx.x] = s[255];
}

__global__ void scan_bsum_kernel(const int* __restrict__ bsum, int* __restrict__ bsum2, int nb) {
    __shared__ int s[256];
    int t = threadIdx.x;
    int v = (t < nb) ? bsum[t] : 0;
    s[t] = v;
    __syncthreads();
    #pragma unroll
    for (int off = 1; off < 256; off <<= 1) {
        int x = (t >= off) ? s[t - off] : 0;
        __syncthreads();
        s[t] += x;
        __syncthreads();
    }
    if (t < nb) bsum2[t] = s[t] - v;   // exclusive
}

__global__ void scan_add_kernel(int* __restrict__ rowptr, const int* __restrict__ bsum2,
                                int* __restrict__ wofs, int n) {
    int i = blockIdx.x * 256 + threadIdx.x;
    if (i < n) {
        int v = rowptr[i + 1] + bsum2[blockIdx.x];
        rowptr[i + 1] = v;
        wofs[i + 1] = v;
    }
    if (i == 0) { rowptr[0] = 0; wofs[0] = 0; }
}

__global__ void scatter_kernel(const int* __restrict__ src, const int* __restrict__ dst,
                               int* __restrict__ wofs, int* __restrict__ col, int E) {
    int e = blockIdx.x * blockDim.x + threadIdx.x;
    if (e < E) {
        int p = atomicAdd(&wofs[dst[e]], 1);
        col[p] = src[e];
    }
}

// ---------------- embedding gather ----------------
__global__ void embed_kernel(const int* __restrict__ x, const float* __restrict__ emb,
                             __nv_bfloat16* __restrict__ hb, int N) {
    int idx = blockIdx.x * blockDim.x + threadIdx.x;
    if (idx >= N * 32) return;
    int n  = idx >> 5;
    int g8 = (idx & 31) << 3;
    const float* p = emb + (size_t)x[n] * EMB + g8;
    float4 a = *(const float4*)p;
    float4 b = *(const float4*)(p + 4);
    __nv_bfloat162 o[4];
    o[0] = __float22bfloat162_rn(make_float2(a.x, a.y));
    o[1] = __float22bfloat162_rn(make_float2(a.z, a.w));
    o[2] = __float22bfloat162_rn(make_float2(b.x, b.y));
    o[3] = __float22bfloat162_rn(make_float2(b.z, b.w));
    *(uint4*)(hb + (size_t)n * EMB + g8) = *(uint4*)o;
}

// ---------------- weight pack: tiled transpose ----------------
__global__ void pack_kernel(const float* __restrict__ Wq, const float* __restrict__ Wk,
                            const float* __restrict__ Wv, const float* __restrict__ Ws,
                            const float* __restrict__ bq, const float* __restrict__ bk,
                            const float* __restrict__ bv, const float* __restrict__ bs,
                            __nv_bfloat16* __restrict__ Wt, float* __restrict__ bcat, int K) {
    __shared__ float t[32][33];
    int n0 = blockIdx.x * 32, k0 = blockIdx.y * 32;
    int tx = threadIdx.x, ty = threadIdx.y;
    #pragma unroll
    for (int i = 0; i < 4; i++) {
        int k = k0 + ty + i * 8;
        int n = n0 + tx;
        float v;
        if (n < 1024)       v = Wq[k * 1024 + n];
        else if (n < 2048)  v = Wk[k * 1024 + (n - 1024)];
        else if (n < 3072)  v = Wv[k * 1024 + (n - 2048)];
        else if (n < NREAL) v = Ws[k * 128  + (n - 3072)];
        else                v = 0.f;
        t[ty + i * 8][tx] = v;
    }
    if (k0 == 0 && ty == 0) {
        int n = n0 + tx;
        float b;
        if (n < 1024)       b = bq[n];
        else if (n < 2048)  b = bk[n - 1024];
        else if (n < 3072)  b = bv[n - 2048];
        else if (n < NREAL) b = bs[n - 3072];
        else                b = 0.f;
        bcat[n] = b;
    }
    __syncthreads();
    #pragma unroll
    for (int i = 0; i < 4; i++) {
        int n = n0 + ty + i * 8;
        int k = k0 + tx;
        Wt[(size_t)n * K + k] = __float2bfloat16(t[tx][ty + i * 8]);
    }
}

// ---------------- bf16 GEMM: 128x128x32, 3-stage ring, ldmatrix, 512 thr (32x32 warp) ----------------
__device__ __forceinline__ void mma_bf16(float* c, const uint32_t* a, const uint32_t* b) {
    asm volatile(
        "mma.sync.aligned.m16n8k16.row.col.f32.bf16.bf16.f32 "
        "{%0,%1,%2,%3}, {%4,%5,%6,%7}, {%8,%9}, {%0,%1,%2,%3};"
        : "+f"(c[0]), "+f"(c[1]), "+f"(c[2]), "+f"(c[3])
        : "r"(a[0]), "r"(a[1]), "r"(a[2]), "r"(a[3]), "r"(b[0]), "r"(b[1]));
}

__device__ __forceinline__ void cp16(uint32_t dst, const void* src) {
    asm volatile("cp.async.cg.shared.global [%0], [%1], 16;" :: "r"(dst), "l"(src));
}

__device__ __forceinline__ void ldsm4(uint32_t& r0, uint32_t& r1, uint32_t& r2, uint32_t& r3,
                                      uint32_t addr) {
    asm volatile("ldmatrix.sync.aligned.m8n8.x4.shared.b16 {%0,%1,%2,%3}, [%4];"
        : "=r"(r0), "=r"(r1), "=r"(r2), "=r"(r3) : "r"(addr));
}

#define GBM 128
#define GBN 128
#define GBK 32
#define RS2 20
#define STG (128 * RS2)
#define STG4 (STG * 4)
#define GEMM_SMEM (6 * STG4)        // 61440 bytes

__device__ __forceinline__ void epi_store(__nv_bfloat16* __restrict__ qb,
                                          __nv_bfloat16* __restrict__ kv,
                                          float* __restrict__ skip,
                                          int r, int c, float2 o) {
    if (c < OFF_K) {
        *(__nv_bfloat162*)(qb + (size_t)r * QB_W + c) = __float22bfloat162_rn(o);
    } else if (c < OFF_S) {
        bool isk = c < OFF_V;
        int ch = isk ? (c - OFF_K) : (c - OFF_V);
        int head = ch >> 7, within = ch & 127;
        int slot = head * 256 + (within >> 2) * 8 + (within & 3) + (isk ? 0 : 4);
        *(__nv_bfloat162*)(kv + (size_t)r * KV_W + slot) = __float22bfloat162_rn(o);
    } else if (c < NREAL) {
        *(float2*)(skip + (size_t)r * CC + (c - OFF_S)) = o;
    }
}

template<int NITER>
__global__ __launch_bounds__(512, 2)
void gemm_bf16_kernel(const __nv_bfloat16* __restrict__ A, const __nv_bfloat16* __restrict__ Bt,
                      const float* __restrict__ bias,
                      __nv_bfloat16* __restrict__ qb, __nv_bfloat16* __restrict__ kv,
                      float* __restrict__ skip, int M, int K) {
    extern __shared__ uint32_t smem[];
    uint32_t sbase = (uint32_t)__cvta_generic_to_shared(smem);

    int bm = blockIdx.y * GBM;
    int bn = blockIdx.x * GBN;
    int tid = threadIdx.x;
    int wid = tid >> 5, lane = tid & 31;
    int wm = (wid >> 2) * 32;
    int wn = (wid & 3) * 32;
    int gid = lane >> 2, tig = lane & 3;

    float acc[2][4][4];
    #pragma unroll
    for (int i = 0; i < 2; i++)
        #pragma unroll
        for (int j = 0; j < 4; j++)
            #pragma unroll
            for (int q = 0; q < 4; q++) acc[i][j][q] = 0.f;

    int lr = tid >> 2, lp = tid & 3;
    int rsafe = min(bm + lr, M - 1);
    const __nv_bfloat16* aPtr = A + (size_t)rsafe * K + lp * 8;
    const __nv_bfloat16* bPtr = Bt + (size_t)(bn + lr) * K + lp * 8;
    uint32_t aD = sbase + (lr * RS2 + lp * 4) * 4;
    uint32_t bD = sbase + 3 * STG4 + (lr * RS2 + lp * 4) * 4;

    int l8 = lane & 7;
    int rowA = l8 + ((lane >> 3) & 1) * 8;
    int colA = (lane >> 4) * 4;
    int rowB = l8 + (lane >> 4) * 8;
    int colB = ((lane >> 3) & 1) * 4;

    cp16(aD, aPtr);
    cp16(bD, bPtr);
    asm volatile("cp.async.commit_group;");
    if (NITER > 1) {
        cp16(aD + STG4, aPtr + 32);
        cp16(bD + STG4, bPtr + 32);
    }
    asm volatile("cp.async.commit_group;");

    #pragma unroll
    for (int it = 0; it < NITER; it++) {
        asm volatile("cp.async.wait_group 1;");
        __syncthreads();
        if (it + 2 < NITER) {
            int s = (it + 2) % 3;
            int kEl = (it + 2) * GBK;
            cp16(aD + s * STG4, aPtr + kEl);
            cp16(bD + s * STG4, bPtr + kEl);
        }
        asm volatile("cp.async.commit_group;");

        uint32_t sA = sbase + (it % 3) * STG4;
        uint32_t sB = sbase + 3 * STG4 + (it % 3) * STG4;
        #pragma unroll
        for (int kk2 = 0; kk2 < 16; kk2 += 8) {
            uint32_t af[2][4], bf[4][2];
            #pragma unroll
            for (int i = 0; i < 2; i++)
                ldsm4(af[i][0], af[i][1], af[i][2], af[i][3],
                      sA + ((wm + i * 16 + rowA) * RS2 + colA + kk2) * 4);
            #pragma unroll
            for (int j = 0; j < 4; j += 2)
                ldsm4(bf[j][0], bf[j][1], bf[j + 1][0], bf[j + 1][1],
                      sB + ((wn + j * 8 + rowB) * RS2 + colB + kk2) * 4);
            #pragma unroll
            for (int i = 0; i < 2; i++)
                #pragma unroll
                for (int j = 0; j < 4; j++)
                    mma_bf16(acc[i][j], af[i], bf[j]);
        }
    }

    #pragma unroll
    for (int i = 0; i < 2; i++) {
        int r0 = bm + wm + i * 16 + gid;
        #pragma unroll
        for (int j = 0; j < 4; j++) {
            int c = bn + wn + j * 8 + tig * 2;
            float2 bb = *(const float2*)(bias + c);
            if (r0 < M)
                epi_store(qb, kv, skip, r0, c,
                          make_float2(acc[i][j][0] + bb.x, acc[i][j][1] + bb.y));
            if (r0 + 8 < M)
                epi_store(qb, kv, skip, r0 + 8, c,
                          make_float2(acc[i][j][2] + bb.x, acc[i][j][3] + bb.y));
        }
    }
}

// ---------------- fused attention + beta-gate + LayerNorm + ReLU (ILP x2) ----------------
__global__ __launch_bounds__(256)
void attn_fused_kernel(const __nv_bfloat16* __restrict__ qb, const __nv_bfloat16* __restrict__ kv,
                       const int* __restrict__ rowptr, const int* __restrict__ col,
                       const float* __restrict__ skip, const float* __restrict__ Wb,
                       const float* __restrict__ gam, const float* __restrict__ bet,
                       const __nv_bfloat16* __restrict__ res, __nv_bfloat16* __restrict__ out) {
    __shared__ float sm[HH * CC + CC];
    int node = blockIdx.x;
    int wid  = threadIdx.x >> 5;
    int lane = threadIdx.x & 31;
    const float scale = 0.0883883476483184f; // 1/sqrt(128)

    uint2 qr = *(const uint2*)(qb + (size_t)node * QB_W + wid * CC + lane * 4);
    float2 qa = __bfloat1622float2(*(const __nv_bfloat162*)&qr.x);
    float2 qc = __bfloat1622float2(*(const __nv_bfloat162*)&qr.y);
    int e0 = rowptr[node], e1 = rowptr[node + 1];
    size_t off = (size_t)wid * 256 + lane * 8;

    float m0 = -1e30f, den0 = 0.f, m1 = -1e30f, den1 = 0.f;
    float4 a0 = make_float4(0.f, 0.f, 0.f, 0.f);
    float4 a1 = make_float4(0.f, 0.f, 0.f, 0.f);

    int e = e0;
    for (; e + 1 < e1; e += 2) {
        int s0 = col[e], s1 = col[e + 1];
        uint4 p0 = *(const uint4*)(kv + (size_t)s0 * KV_W + off);
        uint4 p1 = *(const uint4*)(kv + (size_t)s1 * KV_W + off);
        float2 k0a = __bfloat1622float2(*(const __nv_bfloat162*)&p0.x);
        float2 k0b = __bfloat1622float2(*(const __nv_bfloat162*)&p0.y);
        float2 k1a = __bfloat1622float2(*(const __nv_bfloat162*)&p1.x);
        float2 k1b = __bfloat1622float2(*(const __nv_bfloat162*)&p1.y);
        float d0 = qa.x * k0a.x + qa.y * k0a.y + qc.x * k0b.x + qc.y * k0b.y;
        float d1 = qa.x * k1a.x + qa.y * k1a.y + qc.x * k1b.x + qc.y * k1b.y;
        #pragma unroll
        for (int o = 16; o; o >>= 1) {
            d0 += __shfl_xor_sync(0xffffffffu, d0, o);
            d1 += __shfl_xor_sync(0xffffffffu, d1, o);
        }
        float2 v0a = __bfloat1622float2(*(const __nv_bfloat162*)&p0.z);
        float2 v0b = __bfloat1622float2(*(const __nv_bfloat162*)&p0.w);
        float2 v1a = __bfloat1622float2(*(const __nv_bfloat162*)&p1.z);
        float2 v1b = __bfloat1622float2(*(const __nv_bfloat162*)&p1.w);
        {
            float lg = d0 * scale;
            float mn = fmaxf(m0, lg);
            float cr = __expf(m0 - mn), p = __expf(lg - mn);
            den0 = den0 * cr + p;
            a0.x = a0.x * cr + p * v0a.x; a0.y = a0.y * cr + p * v0a.y;
            a0.z = a0.z * cr + p * v0b.x; a0.w = a0.w * cr + p * v0b.y;
            m0 = mn;
        }
        {
            float lg = d1 * scale;
            float mn = fmaxf(m1, lg);
            float cr = __expf(m1 - mn), p = __expf(lg - mn);
            den1 = den1 * cr + p;
            a1.x = a1.x * cr + p * v1a.x; a1.y = a1.y * cr + p * v1a.y;
            a1.z = a1.z * cr + p * v1b.x; a1.w = a1.w * cr + p * v1b.y;
            m1 = mn;
        }
    }
    if (e < e1) {
        int s0 = col[e];
        uint4 p0 = *(const uint4*)(kv + (size_t)s0 * KV_W + off);
        float2 k0a = __bfloat1622float2(*(const __nv_bfloat162*)&p0.x);
        float2 k0b = __bfloat1622float2(*(const __nv_bfloat162*)&p0.y);
        float d0 = qa.x * k0a.x + qa.y * k0a.y + qc.x * k0b.x + qc.y * k0b.y;
        #pragma unroll
        for (int o = 16; o; o >>= 1) d0 += __shfl_xor_sync(0xffffffffu, d0, o);
        float2 v0a = __bfloat1622float2(*(const __nv_bfloat162*)&p0.z);
        float2 v0b = __bfloat1622float2(*(const __nv_bfloat162*)&p0.w);
        float lg = d0 * scale;
        float mn = fmaxf(m0, lg);
        float cr = __expf(m0 - mn), p = __expf(lg - mn);
        den0 = den0 * cr + p;
        a0.x = a0.x * cr + p * v0a.x; a0.y = a0.y * cr + p * v0a.y;
        a0.z = a0.z * cr + p * v0b.x; a0.w = a0.w * cr + p * v0b.y;
        m0 = mn;
    }
    float M = fmaxf(m0, m1);
    float c0 = __expf(m0 - M), c1 = __expf(m1 - M);
    float den = den0 * c0 + den1 * c1;
    float4 acc;
    acc.x = a0.x * c0 + a1.x * c1;
    acc.y = a0.y * c0 + a1.y * c1;
    acc.z = a0.z * c0 + a1.z * c1;
    acc.w = a0.w * c0 + a1.w * c1;

    float inv = 1.f / (den + 1e-16f);
    sm[wid * CC + lane * 4 + 0] = acc.x * inv;
    sm[wid * CC + lane * 4 + 1] = acc.y * inv;
    sm[wid * CC + lane * 4 + 2] = acc.z * inv;
    sm[wid * CC + lane * 4 + 3] = acc.w * inv;
    __syncthreads();

    if (threadIdx.x < CC) {
        float s = 0.f;
        #pragma unroll
        for (int h = 0; h < HH; h++) s += sm[h * CC + threadIdx.x];
        sm[HH * CC + threadIdx.x] = s * 0.125f;
    }
    __syncthreads();

    if (threadIdx.x < 32) {
        int c = threadIdx.x * 4;
        float4 a  = *(float4*)&sm[HH * CC + c];
        float4 xr = *(const float4*)(skip + (size_t)node * CC + c);
        float4 w0 = *(const float4*)(Wb + c);
        float4 w1 = *(const float4*)(Wb + 128 + c);
        float4 w2 = *(const float4*)(Wb + 256 + c);

        float t = a.x * w0.x + a.y * w0.y + a.z * w0.z + a.w * w0.w
                + xr.x * w1.x + xr.y * w1.y + xr.z * w1.z + xr.w * w1.w
                + (a.x - xr.x) * w2.x + (a.y - xr.y) * w2.y
                + (a.z - xr.z) * w2.z + (a.w - xr.w) * w2.w;
        #pragma unroll
        for (int o = 16; o; o >>= 1) t += __shfl_xor_sync(0xffffffffu, t, o);
        float beta = 1.f / (1.f + __expf(-t));

        float4 y;
        y.x = beta * xr.x + (1.f - beta) * a.x;
        y.y = beta * xr.y + (1.f - beta) * a.y;
        y.z = beta * xr.z + (1.f - beta) * a.z;
        y.w = beta * xr.w + (1.f - beta) * a.w;
        if (res) {
            uint2 rr = *(const uint2*)(res + (size_t)node * CC + c);
            float2 r0 = __bfloat1622float2(*(const __nv_bfloat162*)&rr.x);
            float2 r1 = __bfloat1622float2(*(const __nv_bfloat162*)&rr.y);
            y.x += r0.x; y.y += r0.y; y.z += r1.x; y.w += r1.y;
        }
        float s = y.x + y.y + y.z + y.w;
        #pragma unroll
        for (int o = 16; o; o >>= 1) s += __shfl_xor_sync(0xffffffffu, s, o);
        float mu = s * (1.f / 128.f);
        float dx0 = y.x - mu, dx1 = y.y - mu, dx2 = y.z - mu, dx3 = y.w - mu;
        float q = dx0 * dx0 + dx1 * dx1 + dx2 * dx2 + dx3 * dx3;
        #pragma unroll
        for (int o = 16; o; o >>= 1) q += __shfl_xor_sync(0xffffffffu, q, o);
        float rstd = rsqrtf(q * (1.f / 128.f) + 1e-5f);
        float4 gg = *(const float4*)(gam + c);
        float4 bb = *(const float4*)(bet + c);
        float2 o0, o1;
        o0.x = fmaxf(dx0 * rstd * gg.x + bb.x, 0.f);
        o0.y = fmaxf(dx1 * rstd * gg.y + bb.y, 0.f);
        o1.x = fmaxf(dx2 * rstd * gg.z + bb.z, 0.f);
        o1.y = fmaxf(dx3 * rstd * gg.w + bb.w, 0.f);
        uint2 ow;
        *(__nv_bfloat162*)&ow.x = __float22bfloat162_rn(o0);
        *(__nv_bfloat162*)&ow.y = __float22bfloat162_rn(o1);
        *(uint2*)(out + (size_t)node * CC + c) = ow;
    }
}

// ---------------- pooling (batch sorted) ----------------
__global__ __launch_bounds__(128)
void pool_kernel(const __nv_bfloat16* __restrict__ h, const int* __restrict__ batch,
                 float* __restrict__ psum, float* __restrict__ cnt, int N) {
    int c = threadIdx.x;
    int n0 = blockIdx.x * 64;
    int n1 = min(n0 + 64, N);
    int cur = batch[n0];
    float s = 0.f;
    float k = 0.f;
    for (int n = n0; n < n1; n++) {
        int b = batch[n];
        if (b != cur) {
            atomicAdd(&psum[cur * CC + c], s);
            if (c == 0) atomicAdd(&cnt[cur], k);
            s = 0.f; k = 0.f; cur = b;
        }
        s += __bfloat162float(h[(size_t)n * CC + c]);
        k += 1.f;
    }
    atomicAdd(&psum[cur * CC + c], s);
    if (c == 0) atomicAdd(&cnt[cur], k);
}

// ---------------- classifier ----------------
__global__ void cls_kernel(const float* __restrict__ psum, const float* __restrict__ cnt,
                           const float* __restrict__ Wc1, const float* __restrict__ bc1,
                           const float* __restrict__ Wc2, const float* __restrict__ bc2,
                           float* __restrict__ out) {
    int g = threadIdx.x;
    if (g >= NG) return;
    float invc = 1.f / fmaxf(cnt[g], 1.f);
    float pooled[CC];
    #pragma unroll 8
    for (int c = 0; c < CC; c++) pooled[c] = psum[g * CC + c] * invc;
    float r = bc2[0];
    for (int j = 0; j < 64; j++) {
        float z = bc1[j];
        #pragma unroll 8
        for (int c = 0; c < CC; c++) z += pooled[c] * Wc1[c * 64 + j];
        r += fmaxf(z, 0.f) * Wc2[j];
    }
    out[g] = r;
}

// ---------------- launch ----------------
extern "C" void kernel_launch(void* const* d_in, const int* in_sizes, int n_in,
                              void* d_out, int out_size) {
    const int N = NN, E = EE;
    const int*   x     = (const int*)d_in[0];
    const int*   ei    = (const int*)d_in[1];
    const int*   src   = ei;
    const int*   dst   = ei + E;
    const int*   batch = (const int*)d_in[2];
    const float* emb   = (const float*)d_in[3];

    const float *Wq0 = (const float*)d_in[4],  *bq0 = (const float*)d_in[5];
    const float *Wk0 = (const float*)d_in[6],  *bk0 = (const float*)d_in[7];
    const float *Wv0 = (const float*)d_in[8],  *bv0 = (const float*)d_in[9];
    const float *Ws0 = (const float*)d_in[10], *bs0 = (const float*)d_in[11];
    const float *Wb0 = (const float*)d_in[12];
    const float *g0  = (const float*)d_in[13], *be0 = (const float*)d_in[14];
    const float *Wq1 = (const float*)d_in[15], *bq1 = (const float*)d_in[16];
    const float *Wk1 = (const float*)d_in[17], *bk1 = (const float*)d_in[18];
    const float *Wv1 = (const float*)d_in[19], *bv1 = (const float*)d_in[20];
    const float *Ws1 = (const float*)d_in[21], *bs1 = (const float*)d_in[22];
    const float *Wb1 = (const float*)d_in[23];
    const float *g1  = (const float*)d_in[24], *be1 = (const float*)d_in[25];
    const float *Wc1 = (const float*)d_in[26], *bc1 = (const float*)d_in[27];
    const float *Wc2 = (const float*)d_in[28], *bc2 = (const float*)d_in[29];

    __nv_bfloat16 *hb, *qbb, *kv, *h1, *h2, *Wt, *Wt1;
    float *skip, *bcat, *bcat1, *pool, *cnt;
    int *deg, *rowptr, *wofs, *col, *bsum, *bsum2;
    cudaGetSymbolAddress((void**)&hb,     g_hb);
    cudaGetSymbolAddress((void**)&qbb,    g_qb);
    cudaGetSymbolAddress((void**)&kv,     g_kv);
    cudaGetSymbolAddress((void**)&skip,   g_skip);
    cudaGetSymbolAddress((void**)&h1,     g_h1);
    cudaGetSymbolAddress((void**)&h2,     g_h2);
    cudaGetSymbolAddress((void**)&Wt,     g_Wt);
    cudaGetSymbolAddress((void**)&Wt1,    g_Wt1);
    cudaGetSymbolAddress((void**)&bcat,   g_bcat);
    cudaGetSymbolAddress((void**)&bcat1,  g_bcat1);
    cudaGetSymbolAddress((void**)&pool,   g_pool);
    cudaGetSymbolAddress((void**)&cnt,    g_cnt);
    cudaGetSymbolAddress((void**)&deg,    g_deg);
    cudaGetSymbolAddress((void**)&rowptr, g_rowptr);
    cudaGetSymbolAddress((void**)&wofs,   g_wofs);
    cudaGetSymbolAddress((void**)&col,    g_col);
    cudaGetSymbolAddress((void**)&bsum,   g_bsum);
    cudaGetSymbolAddress((void**)&bsum2,  g_bsum2);

    cudaFuncSetAttribute(gemm_bf16_kernel<8>, cudaFuncAttributeMaxDynamicSharedMemorySize,
                         GEMM_SMEM);
    cudaFuncSetAttribute(gemm_bf16_kernel<4>, cudaFuncAttributeMaxDynamicSharedMemorySize,
                         GEMM_SMEM);

    const int NB = (N + 255) / 256;
    dim3 ggrid(NOUT / GBN, (N + GBM - 1) / GBM);   // (26, 391)
    dim3 pgrid(NOUT / 32, 256 / 32);
    dim3 pgrid1(NOUT / 32, 128 / 32);
    dim3 pthr(32, 8);

    // side stream (capture-forked via events); created fresh per call (few calls total)
    cudaStream_t s1;
    cudaStreamCreate(&s1);
    cudaEvent_t evFork, evJoin;
    cudaEventCreateWithFlags(&evFork, cudaEventDisableTiming);
    cudaEventCreateWithFlags(&evJoin, cudaEventDisableTiming);

    // fork side stream off the capture (legacy) stream
    cudaEventRecord(evFork, 0);
    cudaStreamWaitEvent(s1, evFork, 0);

    // ---- launch order keeps gemm0 in the profiled slot (#6 incl. harness poison memset) ----
    cudaMemsetAsync(deg, 0, N * sizeof(int), s1);                               // 1
    hist_kernel<<<(E + 255) / 256, 256, 0, s1>>>(dst, deg, E);                  // 2
    embed_kernel<<<(N * 32 + 255) / 256, 256>>>(x, emb, hb, N);                 // 3
    pack_kernel<<<pgrid, pthr>>>(Wq0, Wk0, Wv0, Ws0, bq0, bk0, bv0, bs0,
                                 Wt, bcat, 256);                                // 4
    gemm_bf16_kernel<8><<<ggrid, 512, GEMM_SMEM>>>(hb, Wt, bcat, qbb, kv, skip,
                                                   N, 256);                     // 5 <- profiled
    // side stream: rest of CSR build + layer-1 pack + pool memsets (overlap gemm0)
    scan_block_kernel<<<NB, 256, 0, s1>>>(deg, rowptr, bsum, N);
    scan_bsum_kernel<<<1, 256, 0, s1>>>(bsum, bsum2, NB);
    scan_add_kernel<<<NB, 256, 0, s1>>>(rowptr, bsum2, wofs, N);
    scatter_kernel<<<(E + 255) / 256, 256, 0, s1>>>(src, dst, wofs, col, E);
    pack_kernel<<<pgrid1, pthr, 0, s1>>>(Wq1, Wk1, Wv1, Ws1, bq1, bk1, bv1, bs1,
                                         Wt1, bcat1, 128);
    cudaMemsetAsync(pool, 0, NG * CC * sizeof(float), s1);
    cudaMemsetAsync(cnt, 0, NG * sizeof(float), s1);
    cudaEventRecord(evJoin, s1);
    cudaStreamWaitEvent(0, evJoin, 0);

    // ---- main chain continues ----
    attn_fused_kernel<<<N, 256>>>(qbb, kv, rowptr, col, skip, Wb0, g0, be0,
                                  (const __nv_bfloat16*)nullptr, h1);
    gemm_bf16_kernel<4><<<ggrid, 512, GEMM_SMEM>>>(h1, Wt1, bcat1, qbb, kv, skip,
                                                   N, 128);
    attn_fused_kernel<<<N, 256>>>(qbb, kv, rowptr, col, skip, Wb1, g1, be1,
                                  h1, h2);
    pool_kernel<<<(N + 63) / 64, 128>>>(h2, batch, pool, cnt, N);
    cls_kernel<<<1, 64>>>(pool, cnt, Wc1, bc1, Wc2, bc2, (float*)d_out);

    cudaStreamDestroy(s1);
}